// round 1
// baseline (speedup 1.0000x reference)
#include <cuda_runtime.h>
#include <cuda_bf16.h>
#include <cstddef>

#define NN    20000
#define EE    320000
#define ET    340000      // EE + NN self loops
#define BB    64
#define IND   768
#define H1D   512
#define NHEADS 4
#define HIDC  128
#define OUTD  256

// ---------------- scratch (device globals: no allocations allowed) ----------
__device__ float    g_h   [(size_t)NN * H1D];   // GEMM output (pre-aggregation features)
__device__ float    g_acc [(size_t)NN * H1D];   // weighted aggregation accumulator
__device__ float    g_feat[(size_t)NN * H1D];   // layer output / next-layer input
__device__ float    g_ssrc[NN * NHEADS];
__device__ float    g_sdst[NN * NHEADS];
__device__ unsigned g_m   [NN * NHEADS];        // encoded segment max
__device__ float    g_den [NN * NHEADS];        // softmax denominator
__device__ float    g_sum [H1D];
__device__ float    g_sumsq[H1D];
__device__ float    g_cnt [BB];

// ---------------- helpers ---------------------------------------------------
__device__ __forceinline__ float lrelu(float v) { return v > 0.f ? v : 0.2f * v; }

// monotone float <-> unsigned mapping for atomicMax
__device__ __forceinline__ unsigned fenc(float f) {
    int i = __float_as_int(f);
    return (i >= 0) ? ((unsigned)i | 0x80000000u) : ~((unsigned)i);
}
__device__ __forceinline__ float fdec(unsigned u) {
    int i = (u & 0x80000000u) ? (int)(u & 0x7FFFFFFFu) : (int)(~u);
    return __int_as_float(i);
}

// ---------------- generic zero ----------------------------------------------
__global__ void zero_f(float* p, int n) {
    int i = blockIdx.x * blockDim.x + threadIdx.x;
    if (i < n) p[i] = 0.f;
}
__global__ void zero_u(unsigned* p, int n) {
    int i = blockIdx.x * blockDim.x + threadIdx.x;
    if (i < n) p[i] = 0u;
}

// ---------------- GEMM: C[NR,K] = A[NR,M] * W[M,K] (row major) --------------
#define GBM 64
#define GBN 64
#define GBK 16
__global__ __launch_bounds__(256) void gemm_k(
    const float* __restrict__ A, const float* __restrict__ W,
    float* __restrict__ C, int NR, int M, int K)
{
    __shared__ float As[GBK][GBM];
    __shared__ float Ws[GBK][GBN];
    int tid = threadIdx.x;
    int tx = tid & 15, ty = tid >> 4;
    int row0 = blockIdx.y * GBM, col0 = blockIdx.x * GBN;

    float acc[4][4] = {};

    for (int k0 = 0; k0 < M; k0 += GBK) {
        // A tile: each thread loads a float4 (row = tid/4, k offset = (tid%4)*4)
        {
            int m  = tid >> 2;
            int kk = (tid & 3) * 4;
            int gr = row0 + m;
            float4 av = make_float4(0.f, 0.f, 0.f, 0.f);
            if (gr < NR) av = *(const float4*)(A + (size_t)gr * M + k0 + kk);
            As[kk + 0][m] = av.x; As[kk + 1][m] = av.y;
            As[kk + 2][m] = av.z; As[kk + 3][m] = av.w;
        }
        // W tile: float4 per thread
        {
            int k  = tid >> 4;
            int n4 = (tid & 15) * 4;
            float4 wv = *(const float4*)(W + (size_t)(k0 + k) * K + col0 + n4);
            Ws[k][n4 + 0] = wv.x; Ws[k][n4 + 1] = wv.y;
            Ws[k][n4 + 2] = wv.z; Ws[k][n4 + 3] = wv.w;
        }
        __syncthreads();
        #pragma unroll
        for (int k = 0; k < GBK; k++) {
            float4 a4 = *(const float4*)&As[k][ty * 4];
            float4 b4 = *(const float4*)&Ws[k][tx * 4];
            float a[4] = {a4.x, a4.y, a4.z, a4.w};
            float b[4] = {b4.x, b4.y, b4.z, b4.w};
            #pragma unroll
            for (int i = 0; i < 4; i++)
                #pragma unroll
                for (int j = 0; j < 4; j++)
                    acc[i][j] += a[i] * b[j];
        }
        __syncthreads();
    }

    #pragma unroll
    for (int i = 0; i < 4; i++) {
        int gr = row0 + ty * 4 + i;
        if (gr >= NR) break;
        float* cp = C + (size_t)gr * K + col0 + tx * 4;
        cp[0] = acc[i][0]; cp[1] = acc[i][1]; cp[2] = acc[i][2]; cp[3] = acc[i][3];
    }
}

// ---------------- per-node attention scores ---------------------------------
// blockDim = heads*32; warp w handles head w of node blockIdx.x
__global__ void scores_k(const float* __restrict__ h,
                         const float* __restrict__ a_s, const float* __restrict__ a_d,
                         float* __restrict__ ss, float* __restrict__ sd,
                         int heads, int C)
{
    int n = blockIdx.x;
    int w = threadIdx.x >> 5, lane = threadIdx.x & 31;
    const float* hp = h + ((size_t)n * heads + w) * C;
    float s1 = 0.f, s2 = 0.f;
    for (int c = lane * 4; c < C; c += 128) {
        float4 hv = *(const float4*)(hp + c);
        float4 av = *(const float4*)(a_s + w * C + c);
        float4 dv = *(const float4*)(a_d + w * C + c);
        s1 += hv.x * av.x + hv.y * av.y + hv.z * av.z + hv.w * av.w;
        s2 += hv.x * dv.x + hv.y * dv.y + hv.z * dv.z + hv.w * dv.w;
    }
    #pragma unroll
    for (int o = 16; o; o >>= 1) {
        s1 += __shfl_xor_sync(0xffffffffu, s1, o);
        s2 += __shfl_xor_sync(0xffffffffu, s2, o);
    }
    if (lane == 0) { ss[n * heads + w] = s1; sd[n * heads + w] = s2; }
}

// ---------------- edge pass 1: segment max ----------------------------------
__global__ void edge_max_k(const int* __restrict__ ei,
                           const float* __restrict__ ss, const float* __restrict__ sd,
                           unsigned* __restrict__ m, int heads)
{
    int t = blockIdx.x * blockDim.x + threadIdx.x;
    if (t >= ET * heads) return;
    int e = t / heads, h = t - e * heads;
    int s, d;
    if (e < EE) { s = ei[e]; d = ei[EE + e]; } else { s = d = e - EE; }
    float v = lrelu(ss[s * heads + h] + sd[d * heads + h]);
    atomicMax(m + d * heads + h, fenc(v));
}

// ---------------- edge pass 2: exp weights + feature scatter ----------------
// grid = ET, blockDim = heads*C/4. Thread t: head = t/(C/4), 4 channels.
__global__ void edge_scatter_k(const int* __restrict__ ei,
                               const float* __restrict__ hfeat,
                               const float* __restrict__ ss, const float* __restrict__ sd,
                               const unsigned* __restrict__ m,
                               float* __restrict__ den, float* __restrict__ acc,
                               int heads, int C)
{
    int e = blockIdx.x;
    int t = threadIdx.x;
    int cq4 = C >> 2;
    int h = t / cq4;
    int cq = t - h * cq4;
    int s, d;
    if (e < EE) { s = ei[e]; d = ei[EE + e]; } else { s = d = e - EE; }
    float v = lrelu(ss[s * heads + h] + sd[d * heads + h]);
    float p = __expf(v - fdec(m[d * heads + h]));
    if (cq == 0) atomicAdd(den + d * heads + h, p);
    float4 hv = *(const float4*)(hfeat + ((size_t)s * heads + h) * C + cq * 4);
    float* dp = acc + ((size_t)d * heads + h) * C + cq * 4;
    atomicAdd(dp + 0, hv.x * p);
    atomicAdd(dp + 1, hv.y * p);
    atomicAdd(dp + 2, hv.z * p);
    atomicAdd(dp + 3, hv.w * p);
}

// ---------------- finalize (layers 1/2): normalize + bias -------------------
__global__ void finalize_k(const float* __restrict__ acc, const float* __restrict__ den,
                           const float* __restrict__ b, float* __restrict__ out)
{
    int idx = blockIdx.x * blockDim.x + threadIdx.x;
    if (idx >= NN * H1D) return;
    int n = idx >> 9;          // /512
    int j = idx & 511;
    int h = j >> 7;            // /128
    out[idx] = acc[idx] / (den[n * NHEADS + h] + 1e-16f) + b[j];
}

// ---------------- batchnorm -------------------------------------------------
__global__ void bn_stats_k(const float* __restrict__ x,
                           float* __restrict__ sum, float* __restrict__ sumsq)
{
    float ls0 = 0.f, ls1 = 0.f, lq0 = 0.f, lq1 = 0.f;
    int t = threadIdx.x;  // 256 threads, D=512 -> 2 channels per thread
    for (int n = blockIdx.x; n < NN; n += gridDim.x) {
        const float* r = x + (size_t)n * H1D;
        float v0 = r[t], v1 = r[t + 256];
        ls0 += v0; lq0 += v0 * v0;
        ls1 += v1; lq1 += v1 * v1;
    }
    atomicAdd(sum + t, ls0);       atomicAdd(sumsq + t, lq0);
    atomicAdd(sum + t + 256, ls1); atomicAdd(sumsq + t + 256, lq1);
}

__global__ void bn_apply_k(float* __restrict__ x,
                           const float* __restrict__ sum, const float* __restrict__ sumsq,
                           const float* __restrict__ gamma, const float* __restrict__ beta)
{
    int idx = blockIdx.x * blockDim.x + threadIdx.x;
    if (idx >= NN * H1D) return;
    int c = idx & 511;
    const float invN = 1.0f / NN;
    float mu = sum[c] * invN;
    float var = sumsq[c] * invN - mu * mu;
    float v = gamma[c] * (x[idx] - mu) * rsqrtf(var + 1e-5f) + beta[c];
    x[idx] = lrelu(v);
}

// ---------------- finalize layer 3: normalize + bias + leaky ----------------
__global__ void finalize3_k(const float* __restrict__ acc, const float* __restrict__ den,
                            const float* __restrict__ b, float* __restrict__ out)
{
    int idx = blockIdx.x * blockDim.x + threadIdx.x;
    if (idx >= NN * OUTD) return;
    int n = idx >> 8;
    int c = idx & 255;
    float v = acc[idx] / (den[n] + 1e-16f) + b[c];
    out[idx] = lrelu(v);
}

// ---------------- pooling ---------------------------------------------------
__global__ void pool_zero_k(float* __restrict__ out, float* __restrict__ cnt)
{
    int i = blockIdx.x * blockDim.x + threadIdx.x;
    if (i < BB * OUTD) out[i] = 0.f;
    if (i < BB) cnt[i] = 0.f;
}
__global__ void pool_acc_k(const float* __restrict__ h3, const int* __restrict__ batch,
                           float* __restrict__ out, float* __restrict__ cnt)
{
    int idx = blockIdx.x * blockDim.x + threadIdx.x;
    if (idx >= NN * OUTD) return;
    int n = idx >> 8, c = idx & 255;
    int b = batch[n];
    atomicAdd(out + b * OUTD + c, h3[idx]);
    if (c == 0) atomicAdd(cnt + b, 1.f);
}
__global__ void pool_div_k(float* __restrict__ out, const float* __restrict__ cnt)
{
    int i = blockIdx.x * blockDim.x + threadIdx.x;
    if (i >= BB * OUTD) return;
    float c = cnt[i >> 8];
    out[i] /= (c > 1.f ? c : 1.f);
}

// ---------------- host orchestration ----------------------------------------
static inline int ceil_div(int a, int b) { return (a + b - 1) / b; }

extern "C" void kernel_launch(void* const* d_in, const int* in_sizes, int n_in,
                              void* d_out, int out_size)
{
    const float* x      = (const float*)d_in[0];
    const int*   ei     = (const int*)  d_in[1];
    const int*   batch  = (const int*)  d_in[2];
    const float* W1     = (const float*)d_in[3];
    const float* asrc1  = (const float*)d_in[4];
    const float* adst1  = (const float*)d_in[5];
    const float* b1     = (const float*)d_in[6];
    const float* gamma1 = (const float*)d_in[7];
    const float* beta1  = (const float*)d_in[8];
    const float* W2     = (const float*)d_in[9];
    const float* asrc2  = (const float*)d_in[10];
    const float* adst2  = (const float*)d_in[11];
    const float* b2     = (const float*)d_in[12];
    const float* gamma2 = (const float*)d_in[13];
    const float* beta2  = (const float*)d_in[14];
    const float* W3     = (const float*)d_in[15];
    const float* asrc3  = (const float*)d_in[16];
    const float* adst3  = (const float*)d_in[17];
    const float* b3     = (const float*)d_in[18];
    float* out = (float*)d_out;

    float *hB, *accB, *featB, *ssB, *sdB, *denB, *sumB, *sumsqB, *cntB;
    unsigned* mB;
    cudaGetSymbolAddress((void**)&hB,    g_h);
    cudaGetSymbolAddress((void**)&accB,  g_acc);
    cudaGetSymbolAddress((void**)&featB, g_feat);
    cudaGetSymbolAddress((void**)&ssB,   g_ssrc);
    cudaGetSymbolAddress((void**)&sdB,   g_sdst);
    cudaGetSymbolAddress((void**)&mB,    g_m);
    cudaGetSymbolAddress((void**)&denB,  g_den);
    cudaGetSymbolAddress((void**)&sumB,  g_sum);
    cudaGetSymbolAddress((void**)&sumsqB,g_sumsq);
    cudaGetSymbolAddress((void**)&cntB,  g_cnt);

    dim3 gemm_blk(256);
    int rowBlocks = ceil_div(NN, GBM);

    // ================= Layer 1: 768 -> 4x128 =================
    gemm_k<<<dim3(H1D / GBN, rowBlocks), gemm_blk>>>(x, W1, hB, NN, IND, H1D);
    scores_k<<<NN, NHEADS * 32>>>(hB, asrc1, adst1, ssB, sdB, NHEADS, HIDC);
    zero_u<<<ceil_div(NN * NHEADS, 256), 256>>>(mB, NN * NHEADS);
    zero_f<<<ceil_div(NN * NHEADS, 256), 256>>>(denB, NN * NHEADS);
    zero_f<<<ceil_div(NN * H1D, 256), 256>>>(accB, NN * H1D);
    edge_max_k<<<ceil_div(ET * NHEADS, 256), 256>>>(ei, ssB, sdB, mB, NHEADS);
    edge_scatter_k<<<ET, NHEADS * (HIDC / 4)>>>(ei, hB, ssB, sdB, mB, denB, accB, NHEADS, HIDC);
    finalize_k<<<ceil_div(NN * H1D, 256), 256>>>(accB, denB, b1, featB);
    zero_f<<<ceil_div(H1D, 256), 256>>>(sumB, H1D);
    zero_f<<<ceil_div(H1D, 256), 256>>>(sumsqB, H1D);
    bn_stats_k<<<256, 256>>>(featB, sumB, sumsqB);
    bn_apply_k<<<ceil_div(NN * H1D, 256), 256>>>(featB, sumB, sumsqB, gamma1, beta1);

    // ================= Layer 2: 512 -> 4x128 =================
    gemm_k<<<dim3(H1D / GBN, rowBlocks), gemm_blk>>>(featB, W2, hB, NN, H1D, H1D);
    scores_k<<<NN, NHEADS * 32>>>(hB, asrc2, adst2, ssB, sdB, NHEADS, HIDC);
    zero_u<<<ceil_div(NN * NHEADS, 256), 256>>>(mB, NN * NHEADS);
    zero_f<<<ceil_div(NN * NHEADS, 256), 256>>>(denB, NN * NHEADS);
    zero_f<<<ceil_div(NN * H1D, 256), 256>>>(accB, NN * H1D);
    edge_max_k<<<ceil_div(ET * NHEADS, 256), 256>>>(ei, ssB, sdB, mB, NHEADS);
    edge_scatter_k<<<ET, NHEADS * (HIDC / 4)>>>(ei, hB, ssB, sdB, mB, denB, accB, NHEADS, HIDC);
    finalize_k<<<ceil_div(NN * H1D, 256), 256>>>(accB, denB, b2, featB);
    zero_f<<<ceil_div(H1D, 256), 256>>>(sumB, H1D);
    zero_f<<<ceil_div(H1D, 256), 256>>>(sumsqB, H1D);
    bn_stats_k<<<256, 256>>>(featB, sumB, sumsqB);
    bn_apply_k<<<ceil_div(NN * H1D, 256), 256>>>(featB, sumB, sumsqB, gamma2, beta2);

    // ================= Layer 3: 512 -> 1x256 =================
    gemm_k<<<dim3(OUTD / GBN, rowBlocks), gemm_blk>>>(featB, W3, hB, NN, H1D, OUTD);
    scores_k<<<NN, 32>>>(hB, asrc3, adst3, ssB, sdB, 1, OUTD);
    zero_u<<<ceil_div(NN, 256), 256>>>(mB, NN);
    zero_f<<<ceil_div(NN, 256), 256>>>(denB, NN);
    zero_f<<<ceil_div(NN * OUTD, 256), 256>>>(accB, NN * OUTD);
    edge_max_k<<<ceil_div(ET, 256), 256>>>(ei, ssB, sdB, mB, 1);
    edge_scatter_k<<<ET, OUTD / 4>>>(ei, hB, ssB, sdB, mB, denB, accB, 1, OUTD);
    finalize3_k<<<ceil_div(NN * OUTD, 256), 256>>>(accB, denB, b3, featB);

    // ================= Global mean pool =================
    pool_zero_k<<<ceil_div(BB * OUTD, 256), 256>>>(out, cntB);
    pool_acc_k<<<ceil_div(NN * OUTD, 256), 256>>>(featB, batch, out, cntB);
    pool_div_k<<<ceil_div(BB * OUTD, 256), 256>>>(out, cntB);
}

// round 2
// speedup vs baseline: 1.3950x; 1.3950x over previous
#include <cuda_runtime.h>
#include <cuda_bf16.h>
#include <cstddef>

#define NN    20000
#define EE    320000
#define ET    340000      // EE + NN self loops
#define BB    64
#define IND   768
#define H1D   512
#define NHEADS 4
#define HIDC  128
#define OUTD  256
#define SMAX  192         // smem cache for per-node incoming edges (deg ~ Poisson(17))

// ---------------- scratch (device globals) ----------------------------------
__device__ float g_h   [(size_t)NN * H1D];   // GEMM output
__device__ float g_feat[(size_t)NN * H1D];   // layer output / next input
__device__ float g_ssrc[NN * NHEADS];
__device__ float g_sdst[NN * NHEADS];
__device__ float g_bn  [2 * H1D];            // [0,512)=sum  [512,1024)=sumsq
__device__ float g_cnt [BB];
// CSR (built once per launch from edge_index, reused for all 3 layers)
__device__ int   g_deg [NN];
__device__ int   g_row [NN + 1];
__device__ int   g_cur [NN];
__device__ int   g_srcs[ET];

__device__ __forceinline__ float lrelu(float v) { return v > 0.f ? v : 0.2f * v; }

// ---------------- CSR build --------------------------------------------------
__global__ void deg_k(const int* __restrict__ ei) {
    int e = blockIdx.x * blockDim.x + threadIdx.x;
    if (e >= ET) return;
    int d = (e < EE) ? ei[EE + e] : (e - EE);
    atomicAdd(&g_deg[d], 1);
}

// single-block exclusive scan of g_deg -> g_row, g_cur; g_row[NN]=ET
#define SCHK 20
__global__ __launch_bounds__(1024) void scan_k() {
    __shared__ int s[1024];
    int t = threadIdx.x;
    int base = t * SCHK;
    int local[SCHK];
    int sum = 0;
    #pragma unroll
    for (int i = 0; i < SCHK; i++) {
        int idx = base + i;
        int v = (idx < NN) ? g_deg[idx] : 0;
        local[i] = sum;
        sum += v;
    }
    s[t] = sum;
    __syncthreads();
    for (int off = 1; off < 1024; off <<= 1) {
        int v = (t >= off) ? s[t - off] : 0;
        __syncthreads();
        s[t] += v;
        __syncthreads();
    }
    int boff = (t > 0) ? s[t - 1] : 0;
    #pragma unroll
    for (int i = 0; i < SCHK; i++) {
        int idx = base + i;
        if (idx < NN) {
            int r = boff + local[i];
            g_row[idx] = r;
            g_cur[idx] = r;
        }
    }
    if (t == 1023) g_row[NN] = s[1023];
}

__global__ void fill_k(const int* __restrict__ ei) {
    int e = blockIdx.x * blockDim.x + threadIdx.x;
    if (e >= ET) return;
    int s, d;
    if (e < EE) { s = ei[e]; d = ei[EE + e]; } else { s = d = e - EE; }
    int p = atomicAdd(&g_cur[d], 1);
    g_srcs[p] = s;
}

// ---------------- GEMM: C[NR,K] = A[NR,M] * W[M,K], 128x128 tiles ------------
#define TM 128
#define TN 128
#define TKB 8
__global__ __launch_bounds__(256) void gemm128_k(
    const float* __restrict__ A, const float* __restrict__ W,
    float* __restrict__ C, int NR, int M, int K)
{
    __shared__ float As[2][TKB][TM];
    __shared__ float Bs[2][TKB][TN];
    int tid = threadIdx.x;
    int tx = tid & 15;          // col group (8 cols each)
    int ty = tid >> 4;          // row group (8 rows each)
    int row0 = blockIdx.y * TM;
    int col0 = blockIdx.x * TN;

    // load indices
    int arow = tid >> 1;            // 0..127
    int ak   = (tid & 1) * 4;       // 0 or 4
    int bk   = tid >> 5;            // 0..7
    int bn   = (tid & 31) * 4;      // 0..124

    float acc[8][8] = {};

    int nkb = M / TKB;

    // preload tile 0
    {
        int gr = row0 + arow;
        float4 av = make_float4(0.f, 0.f, 0.f, 0.f);
        if (gr < NR) av = *(const float4*)(A + (size_t)gr * M + ak);
        As[0][ak + 0][arow] = av.x; As[0][ak + 1][arow] = av.y;
        As[0][ak + 2][arow] = av.z; As[0][ak + 3][arow] = av.w;
        float4 wv = *(const float4*)(W + (size_t)bk * K + col0 + bn);
        *(float4*)&Bs[0][bk][bn] = wv;
    }
    __syncthreads();

    for (int kb = 0; kb < nkb; kb++) {
        int cur = kb & 1, nxt = cur ^ 1;
        float4 av, wv;
        bool more = (kb + 1 < nkb);
        if (more) {
            int k0 = (kb + 1) * TKB;
            int gr = row0 + arow;
            av = make_float4(0.f, 0.f, 0.f, 0.f);
            if (gr < NR) av = *(const float4*)(A + (size_t)gr * M + k0 + ak);
            wv = *(const float4*)(W + (size_t)(k0 + bk) * K + col0 + bn);
        }
        #pragma unroll
        for (int k = 0; k < TKB; k++) {
            float4 a0 = *(const float4*)&As[cur][k][ty * 8];
            float4 a1 = *(const float4*)&As[cur][k][ty * 8 + 4];
            float4 b0 = *(const float4*)&Bs[cur][k][tx * 8];
            float4 b1 = *(const float4*)&Bs[cur][k][tx * 8 + 4];
            float a[8] = {a0.x, a0.y, a0.z, a0.w, a1.x, a1.y, a1.z, a1.w};
            float b[8] = {b0.x, b0.y, b0.z, b0.w, b1.x, b1.y, b1.z, b1.w};
            #pragma unroll
            for (int i = 0; i < 8; i++)
                #pragma unroll
                for (int j = 0; j < 8; j++)
                    acc[i][j] += a[i] * b[j];
        }
        if (more) {
            As[nxt][ak + 0][arow] = av.x; As[nxt][ak + 1][arow] = av.y;
            As[nxt][ak + 2][arow] = av.z; As[nxt][ak + 3][arow] = av.w;
            *(float4*)&Bs[nxt][bk][bn] = wv;
        }
        __syncthreads();
    }

    #pragma unroll
    for (int i = 0; i < 8; i++) {
        int gr = row0 + ty * 8 + i;
        if (gr >= NR) break;
        float* cp = C + (size_t)gr * K + col0 + tx * 8;
        *(float4*)(cp)     = make_float4(acc[i][0], acc[i][1], acc[i][2], acc[i][3]);
        *(float4*)(cp + 4) = make_float4(acc[i][4], acc[i][5], acc[i][6], acc[i][7]);
    }
}

// ---------------- per-node attention scores ----------------------------------
__global__ void scores_k(const float* __restrict__ h,
                         const float* __restrict__ a_s, const float* __restrict__ a_d,
                         float* __restrict__ ss, float* __restrict__ sd,
                         int heads, int C)
{
    int n = blockIdx.x;
    int w = threadIdx.x >> 5, lane = threadIdx.x & 31;
    const float* hp = h + ((size_t)n * heads + w) * C;
    float s1 = 0.f, s2 = 0.f;
    for (int c = lane * 4; c < C; c += 128) {
        float4 hv = *(const float4*)(hp + c);
        float4 av = *(const float4*)(a_s + w * C + c);
        float4 dv = *(const float4*)(a_d + w * C + c);
        s1 += hv.x * av.x + hv.y * av.y + hv.z * av.z + hv.w * av.w;
        s2 += hv.x * dv.x + hv.y * dv.y + hv.z * dv.z + hv.w * dv.w;
    }
    #pragma unroll
    for (int o = 16; o; o >>= 1) {
        s1 += __shfl_xor_sync(0xffffffffu, s1, o);
        s2 += __shfl_xor_sync(0xffffffffu, s2, o);
    }
    if (lane == 0) { ss[n * heads + w] = s1; sd[n * heads + w] = s2; }
}

// ---------------- CSR aggregation: softmax + gather-reduce + bias ------------
// grid = NN, blockDim = heads*C/4 (128 for layers 1/2; 64 for layer 3)
__global__ void agg_k(const float* __restrict__ hmat,
                      const float* __restrict__ ss, const float* __restrict__ sd,
                      const float* __restrict__ bias, float* __restrict__ out,
                      int heads, int C, int applyLrelu)
{
    __shared__ float s_p[SMAX * NHEADS];
    __shared__ int   s_src[SMAX];
    __shared__ float s_mx[NHEADS], s_den[NHEADS];

    int n = blockIdx.x;
    int tid = threadIdx.x;
    int row0 = g_row[n];
    int deg = g_row[n + 1] - row0;

    // load src list into smem
    int degc = deg < SMAX ? deg : SMAX;
    for (int i = tid; i < degc; i += blockDim.x) s_src[i] = g_srcs[row0 + i];
    __syncthreads();

    int w = tid >> 5, lane = tid & 31;
    if (w < heads) {
        float sdv = sd[n * heads + w];
        float mx = -3.4e38f;
        for (int i = lane; i < deg; i += 32) {
            int s = (i < SMAX) ? s_src[i] : g_srcs[row0 + i];
            float e = lrelu(ss[s * heads + w] + sdv);
            if (i < SMAX) s_p[i * heads + w] = e;
            mx = fmaxf(mx, e);
        }
        #pragma unroll
        for (int o = 16; o; o >>= 1) mx = fmaxf(mx, __shfl_xor_sync(0xffffffffu, mx, o));
        float den = 0.f;
        for (int i = lane; i < deg; i += 32) {
            float e = (i < SMAX) ? s_p[i * heads + w]
                                 : lrelu(ss[g_srcs[row0 + i] * heads + w] + sdv);
            float p = __expf(e - mx);
            if (i < SMAX) s_p[i * heads + w] = p;
            den += p;
        }
        #pragma unroll
        for (int o = 16; o; o >>= 1) den += __shfl_xor_sync(0xffffffffu, den, o);
        if (lane == 0) { s_mx[w] = mx; s_den[w] = den; }
    }
    __syncthreads();

    int cpq = C >> 2;
    int h = tid / cpq;
    int cq = tid - h * cpq;
    float mx = s_mx[h];
    float inv = 1.f / (s_den[h] + 1e-16f);
    float sdv = sd[n * heads + h];
    float4 acc = make_float4(0.f, 0.f, 0.f, 0.f);
    for (int i = 0; i < deg; i++) {
        int s = (i < SMAX) ? s_src[i] : g_srcs[row0 + i];
        float p = (i < SMAX) ? s_p[i * heads + h]
                             : __expf(lrelu(ss[s * heads + h] + sdv) - mx);
        float a = p * inv;
        float4 v = *(const float4*)(hmat + ((size_t)s * heads + h) * C + cq * 4);
        acc.x += v.x * a; acc.y += v.y * a; acc.z += v.z * a; acc.w += v.w * a;
    }
    int j = h * C + cq * 4;
    float4 bb = *(const float4*)(bias + j);
    acc.x += bb.x; acc.y += bb.y; acc.z += bb.z; acc.w += bb.w;
    if (applyLrelu) {
        acc.x = lrelu(acc.x); acc.y = lrelu(acc.y);
        acc.z = lrelu(acc.z); acc.w = lrelu(acc.w);
    }
    *(float4*)(out + (size_t)n * heads * C + j) = acc;
}

// ---------------- batchnorm --------------------------------------------------
__global__ void bn_stats_k(const float* __restrict__ x, float* __restrict__ bn)
{
    float ls0 = 0.f, ls1 = 0.f, lq0 = 0.f, lq1 = 0.f;
    int t = threadIdx.x;  // 256 threads, 512 channels -> 2 per thread
    for (int n = blockIdx.x; n < NN; n += gridDim.x) {
        const float* r = x + (size_t)n * H1D;
        float v0 = r[t], v1 = r[t + 256];
        ls0 += v0; lq0 += v0 * v0;
        ls1 += v1; lq1 += v1 * v1;
    }
    atomicAdd(bn + t, ls0);             atomicAdd(bn + t + 256, ls1);
    atomicAdd(bn + 512 + t, lq0);       atomicAdd(bn + 512 + t + 256, lq1);
}

__global__ void bn_apply_k(float* __restrict__ x, const float* __restrict__ bn,
                           const float* __restrict__ gamma, const float* __restrict__ beta)
{
    int idx = blockIdx.x * blockDim.x + threadIdx.x;
    if (idx >= NN * H1D) return;
    int c = idx & 511;
    const float invN = 1.0f / NN;
    float mu = bn[c] * invN;
    float var = bn[512 + c] * invN - mu * mu;
    float v = gamma[c] * (x[idx] - mu) * rsqrtf(var + 1e-5f) + beta[c];
    x[idx] = lrelu(v);
}

// ---------------- pooling ----------------------------------------------------
__global__ void pool_acc_k(const float* __restrict__ h3, const int* __restrict__ batch,
                           float* __restrict__ out, float* __restrict__ cnt)
{
    int idx = blockIdx.x * blockDim.x + threadIdx.x;
    if (idx >= NN * OUTD) return;
    int n = idx >> 8, c = idx & 255;
    int b = batch[n];
    atomicAdd(out + b * OUTD + c, h3[idx]);
    if (c == 0) atomicAdd(cnt + b, 1.f);
}
__global__ void pool_div_k(float* __restrict__ out, const float* __restrict__ cnt)
{
    int i = blockIdx.x * blockDim.x + threadIdx.x;
    if (i >= BB * OUTD) return;
    float c = cnt[i >> 8];
    out[i] /= (c > 1.f ? c : 1.f);
}

// ---------------- host orchestration ----------------------------------------
static inline int ceil_div(int a, int b) { return (a + b - 1) / b; }

extern "C" void kernel_launch(void* const* d_in, const int* in_sizes, int n_in,
                              void* d_out, int out_size)
{
    const float* x      = (const float*)d_in[0];
    const int*   ei     = (const int*)  d_in[1];
    const int*   batch  = (const int*)  d_in[2];
    const float* W1     = (const float*)d_in[3];
    const float* asrc1  = (const float*)d_in[4];
    const float* adst1  = (const float*)d_in[5];
    const float* b1     = (const float*)d_in[6];
    const float* gamma1 = (const float*)d_in[7];
    const float* beta1  = (const float*)d_in[8];
    const float* W2     = (const float*)d_in[9];
    const float* asrc2  = (const float*)d_in[10];
    const float* adst2  = (const float*)d_in[11];
    const float* b2     = (const float*)d_in[12];
    const float* gamma2 = (const float*)d_in[13];
    const float* beta2  = (const float*)d_in[14];
    const float* W3     = (const float*)d_in[15];
    const float* asrc3  = (const float*)d_in[16];
    const float* adst3  = (const float*)d_in[17];
    const float* b3     = (const float*)d_in[18];
    float* out = (float*)d_out;

    float *hB, *featB, *ssB, *sdB, *bnB, *cntB;
    int *degB;
    cudaGetSymbolAddress((void**)&hB,    g_h);
    cudaGetSymbolAddress((void**)&featB, g_feat);
    cudaGetSymbolAddress((void**)&ssB,   g_ssrc);
    cudaGetSymbolAddress((void**)&sdB,   g_sdst);
    cudaGetSymbolAddress((void**)&bnB,   g_bn);
    cudaGetSymbolAddress((void**)&cntB,  g_cnt);
    cudaGetSymbolAddress((void**)&degB,  g_deg);

    int rowBlocks = ceil_div(NN, TM);

    // ---- CSR build (reused by all 3 layers) ----
    cudaMemsetAsync(degB, 0, NN * sizeof(int));
    deg_k <<<ceil_div(ET, 256), 256>>>(ei);
    scan_k<<<1, 1024>>>();
    fill_k<<<ceil_div(ET, 256), 256>>>(ei);

    // ================= Layer 1: 768 -> 4x128 =================
    gemm128_k<<<dim3(H1D / TN, rowBlocks), 256>>>(x, W1, hB, NN, IND, H1D);
    scores_k<<<NN, NHEADS * 32>>>(hB, asrc1, adst1, ssB, sdB, NHEADS, HIDC);
    agg_k<<<NN, NHEADS * (HIDC / 4)>>>(hB, ssB, sdB, b1, featB, NHEADS, HIDC, 0);
    cudaMemsetAsync(bnB, 0, 2 * H1D * sizeof(float));
    bn_stats_k<<<256, 256>>>(featB, bnB);
    bn_apply_k<<<ceil_div(NN * H1D, 256), 256>>>(featB, bnB, gamma1, beta1);

    // ================= Layer 2: 512 -> 4x128 =================
    gemm128_k<<<dim3(H1D / TN, rowBlocks), 256>>>(featB, W2, hB, NN, H1D, H1D);
    scores_k<<<NN, NHEADS * 32>>>(hB, asrc2, adst2, ssB, sdB, NHEADS, HIDC);
    agg_k<<<NN, NHEADS * (HIDC / 4)>>>(hB, ssB, sdB, b2, featB, NHEADS, HIDC, 0);
    cudaMemsetAsync(bnB, 0, 2 * H1D * sizeof(float));
    bn_stats_k<<<256, 256>>>(featB, bnB);
    bn_apply_k<<<ceil_div(NN * H1D, 256), 256>>>(featB, bnB, gamma2, beta2);

    // ================= Layer 3: 512 -> 1x256 =================
    gemm128_k<<<dim3(OUTD / TN, rowBlocks), 256>>>(featB, W3, hB, NN, H1D, OUTD);
    scores_k<<<NN, 32>>>(hB, asrc3, adst3, ssB, sdB, 1, OUTD);
    agg_k<<<NN, OUTD / 4>>>(hB, ssB, sdB, b3, featB, 1, OUTD, 1);

    // ================= Global mean pool =================
    cudaMemsetAsync(out, 0, (size_t)BB * OUTD * sizeof(float));
    cudaMemsetAsync(cntB, 0, BB * sizeof(float));
    pool_acc_k<<<ceil_div(NN * OUTD, 256), 256>>>(featB, batch, out, cntB);
    pool_div_k<<<ceil_div(BB * OUTD, 256), 256>>>(out, cntB);
}

// round 4
// speedup vs baseline: 2.7835x; 1.9953x over previous
#include <cuda_runtime.h>
#include <cuda_bf16.h>
#include <cstdint>
#include <cstddef>

#define NN    20000
#define EE    320000
#define ET    340000
#define BB    64
#define IND   768
#define H1D   512
#define NHEADS 4
#define HIDC  128
#define OUTD  256
#define SMAX  192

// ---------------- scratch (device globals) ----------------------------------
__device__ float g_h   [(size_t)NN * H1D];
__device__ float g_feat[(size_t)NN * H1D];
__device__ float g_wt  [(size_t)IND * H1D];   // transposed weights (reused per layer)
__device__ float g_ssrc[NN * NHEADS];
__device__ float g_sdst[NN * NHEADS];
__device__ float g_bn  [2 * H1D];
__device__ float g_cnt [BB];
__device__ int   g_deg [NN];
__device__ int   g_row [NN + 1];
__device__ int   g_cur [NN];
__device__ int   g_srcs[ET];

__device__ __forceinline__ float lrelu(float v) { return v > 0.f ? v : 0.2f * v; }

// pack two floats -> bf16x2 (x -> low half, y -> high half)
__device__ __forceinline__ uint32_t packbf(float x, float y) {
    uint32_t r;
    asm("cvt.rn.bf16x2.f32 %0, %1, %2;" : "=r"(r) : "f"(y), "f"(x));
    return r;
}
__device__ __forceinline__ float bflo(uint32_t u) {
    __nv_bfloat16 b = *reinterpret_cast<__nv_bfloat16*>(&u);
    return __bfloat162float(b);
}
__device__ __forceinline__ float bfhi(uint32_t u) {
    uint32_t h = u >> 16;
    __nv_bfloat16 b = *reinterpret_cast<__nv_bfloat16*>(&h);
    return __bfloat162float(b);
}

#define LDSM4(r0, r1, r2, r3, addr) \
    asm volatile("ldmatrix.sync.aligned.m8n8.x4.shared.b16 {%0,%1,%2,%3}, [%4];" \
        : "=r"(r0), "=r"(r1), "=r"(r2), "=r"(r3) : "r"(addr))

#define MMA_BF16(d, a, b) \
    asm volatile("mma.sync.aligned.m16n8k16.row.col.f32.bf16.bf16.f32 " \
        "{%0,%1,%2,%3}, {%4,%5,%6,%7}, {%8,%9}, {%0,%1,%2,%3};" \
        : "+f"((d)[0]), "+f"((d)[1]), "+f"((d)[2]), "+f"((d)[3]) \
        : "r"((a)[0]), "r"((a)[1]), "r"((a)[2]), "r"((a)[3]), "r"((b)[0]), "r"((b)[1]))

__device__ __forceinline__ uint32_t smem_u32(const void* p) {
    uint32_t a;
    asm("{ .reg .u64 t; cvta.to.shared.u64 t, %1; cvt.u32.u64 %0, t; }" : "=r"(a) : "l"(p));
    return a;
}

// ---------------- CSR build --------------------------------------------------
__global__ void deg_k(const int* __restrict__ ei) {
    int e = blockIdx.x * blockDim.x + threadIdx.x;
    if (e >= ET) return;
    int d = (e < EE) ? ei[EE + e] : (e - EE);
    atomicAdd(&g_deg[d], 1);
}
#define SCHK 20
__global__ __launch_bounds__(1024) void scan_k() {
    __shared__ int s[1024];
    int t = threadIdx.x;
    int base = t * SCHK;
    int local[SCHK];
    int sum = 0;
    #pragma unroll
    for (int i = 0; i < SCHK; i++) {
        int idx = base + i;
        int v = (idx < NN) ? g_deg[idx] : 0;
        local[i] = sum;
        sum += v;
    }
    s[t] = sum;
    __syncthreads();
    for (int off = 1; off < 1024; off <<= 1) {
        int v = (t >= off) ? s[t - off] : 0;
        __syncthreads();
        s[t] += v;
        __syncthreads();
    }
    int boff = (t > 0) ? s[t - 1] : 0;
    #pragma unroll
    for (int i = 0; i < SCHK; i++) {
        int idx = base + i;
        if (idx < NN) {
            int r = boff + local[i];
            g_row[idx] = r;
            g_cur[idx] = r;
        }
    }
    if (t == 1023) g_row[NN] = s[1023];
}
__global__ void fill_k(const int* __restrict__ ei) {
    int e = blockIdx.x * blockDim.x + threadIdx.x;
    if (e >= ET) return;
    int s, d;
    if (e < EE) { s = ei[e]; d = ei[EE + e]; } else { s = d = e - EE; }
    int p = atomicAdd(&g_cur[d], 1);
    g_srcs[p] = s;
}

// ---------------- weight transpose: W[M,K] -> WT[K,M] ------------------------
__global__ void transpose_k(const float* __restrict__ W, float* __restrict__ WT, int M, int K)
{
    __shared__ float t[32][33];
    int x = blockIdx.x * 32 + threadIdx.x;
    int y0 = blockIdx.y * 32;
    for (int i = threadIdx.y; i < 32; i += 8)
        t[i][threadIdx.x] = W[(size_t)(y0 + i) * K + x];
    __syncthreads();
    int xo = y0 + threadIdx.x;
    int yo0 = blockIdx.x * 32;
    for (int i = threadIdx.y; i < 32; i += 8)
        WT[(size_t)(yo0 + i) * M + xo] = t[threadIdx.x][i];
}

// ---------------- bf16-split tensor-core GEMM --------------------------------
// C[NR,KO] = A[NR,KD] * W[KD,KO], WT[KO,KD] pre-transposed.
// CTA tile 128x128, K-chunk 32. SMEM row layout: 128 rows x 128B
// (hi bf16 cols [0,32) at bytes [0,64), lo at bytes [64,128)), XOR swizzle.
// 8 warps: warp tile 64(m) x 32(n): m0=(wid/4)*64, n0=(wid%4)*32.
#define TILEB 16384
#define GEMM_SMEM (4 * TILEB)

__device__ __forceinline__ uint32_t swoff(int r, int cByte) {
    return (uint32_t)(r * 128 + (cByte ^ ((r & 7) << 4)));
}

__global__ __launch_bounds__(256, 1) void gemm_mma_k(
    const float* __restrict__ A, const float* __restrict__ WT,
    float* __restrict__ C, int NR, int KD, int KO)
{
    extern __shared__ char smem[];
    uint32_t sA = smem_u32(smem);            // A: bufs at 0, TILEB
    uint32_t sB = sA + 2 * TILEB;            // B: bufs at 0, TILEB
    const int tid = threadIdx.x;
    const int wid = tid >> 5, lane = tid & 31;
    const int row0 = blockIdx.y * 128, col0 = blockIdx.x * 128;
    const int m0 = (wid >> 2) * 64, n0 = (wid & 3) * 32;

    // loader indices: thread handles 4 float4 per operand per chunk
    // q = tid + j*256 -> r = q>>3 (0..127), kq = (q&7)*4
    float4 stA[4], stB[4];
    const int nc = KD / 32;

    // ldmatrix per-lane address components
    const int arow = (lane & 15);                 // A local row
    const int acb  = ((lane >> 4) & 1) * 16;      // A chunk byte
    const int brow = (lane & 7) + ((lane >> 4) & 1) * 8;  // B local row
    const int bcb  = ((lane >> 3) & 1) * 16;      // B chunk byte

    float d[4][4][4];
    #pragma unroll
    for (int i = 0; i < 4; i++)
        #pragma unroll
        for (int j = 0; j < 4; j++)
            { d[i][j][0] = 0.f; d[i][j][1] = 0.f; d[i][j][2] = 0.f; d[i][j][3] = 0.f; }

    // ---- load chunk 0 into regs, store to buf 0 ----
    #pragma unroll
    for (int j = 0; j < 4; j++) {
        int q = tid + j * 256;
        int r = q >> 3, kq = (q & 7) * 4;
        int gr = row0 + r;
        stA[j] = make_float4(0.f, 0.f, 0.f, 0.f);
        if (gr < NR) stA[j] = *(const float4*)(A + (size_t)gr * KD + kq);
        stB[j] = *(const float4*)(WT + (size_t)(col0 + r) * KD + kq);
    }
    {
        #pragma unroll
        for (int j = 0; j < 4; j++) {
            int q = tid + j * 256;
            int r = q >> 3, kq = (q & 7) * 4;
            // A
            uint32_t h0 = packbf(stA[j].x, stA[j].y);
            uint32_t h1 = packbf(stA[j].z, stA[j].w);
            uint32_t l0 = packbf(stA[j].x - bflo(h0), stA[j].y - bfhi(h0));
            uint32_t l1 = packbf(stA[j].z - bflo(h1), stA[j].w - bfhi(h1));
            *(uint2*)(smem + swoff(r, kq * 2))      = make_uint2(h0, h1);
            *(uint2*)(smem + swoff(r, 64 + kq * 2)) = make_uint2(l0, l1);
            // B
            h0 = packbf(stB[j].x, stB[j].y);
            h1 = packbf(stB[j].z, stB[j].w);
            l0 = packbf(stB[j].x - bflo(h0), stB[j].y - bfhi(h0));
            l1 = packbf(stB[j].z - bflo(h1), stB[j].w - bfhi(h1));
            *(uint2*)(smem + 2 * TILEB + swoff(r, kq * 2))      = make_uint2(h0, h1);
            *(uint2*)(smem + 2 * TILEB + swoff(r, 64 + kq * 2)) = make_uint2(l0, l1);
        }
    }
    __syncthreads();

    for (int c = 0; c < nc; c++) {
        int buf = c & 1;
        uint32_t aBase = sA + buf * TILEB;
        uint32_t bBase = sB + buf * TILEB;
        bool more = (c + 1 < nc);

        if (more) {
            int k0 = (c + 1) * 32;
            #pragma unroll
            for (int j = 0; j < 4; j++) {
                int q = tid + j * 256;
                int r = q >> 3, kq = (q & 7) * 4;
                int gr = row0 + r;
                stA[j] = make_float4(0.f, 0.f, 0.f, 0.f);
                if (gr < NR) stA[j] = *(const float4*)(A + (size_t)gr * KD + k0 + kq);
                stB[j] = *(const float4*)(WT + (size_t)(col0 + r) * KD + k0 + kq);
            }
        }

        #pragma unroll
        for (int s = 0; s < 2; s++) {
            uint32_t Ah[4][4], Al[4][4], Bh[4][2], Bl[4][2];
            // A frags: hi (h=0) and lo (h=1)
            #pragma unroll
            for (int mt = 0; mt < 4; mt++) {
                int r = m0 + mt * 16 + arow;
                LDSM4(Ah[mt][0], Ah[mt][1], Ah[mt][2], Ah[mt][3],
                      aBase + swoff(r, s * 32 + acb));
                LDSM4(Al[mt][0], Al[mt][1], Al[mt][2], Al[mt][3],
                      aBase + swoff(r, 64 + s * 32 + acb));
            }
            // B frags: each x4 covers two n-tiles
            #pragma unroll
            for (int p = 0; p < 2; p++) {
                int r = n0 + p * 16 + brow;
                LDSM4(Bh[2 * p][0], Bh[2 * p][1], Bh[2 * p + 1][0], Bh[2 * p + 1][1],
                      bBase + swoff(r, s * 32 + bcb));
                LDSM4(Bl[2 * p][0], Bl[2 * p][1], Bl[2 * p + 1][0], Bl[2 * p + 1][1],
                      bBase + swoff(r, 64 + s * 32 + bcb));
            }
            #pragma unroll
            for (int mt = 0; mt < 4; mt++)
                #pragma unroll
                for (int nt = 0; nt < 4; nt++) {
                    MMA_BF16(d[mt][nt], Ah[mt], Bh[nt]);
                    MMA_BF16(d[mt][nt], Ah[mt], Bl[nt]);
                    MMA_BF16(d[mt][nt], Al[mt], Bh[nt]);
                }
        }

        if (more) {
            int nb = buf ^ 1;
            #pragma unroll
            for (int j = 0; j < 4; j++) {
                int q = tid + j * 256;
                int r = q >> 3, kq = (q & 7) * 4;
                uint32_t h0 = packbf(stA[j].x, stA[j].y);
                uint32_t h1 = packbf(stA[j].z, stA[j].w);
                uint32_t l0 = packbf(stA[j].x - bflo(h0), stA[j].y - bfhi(h0));
                uint32_t l1 = packbf(stA[j].z - bflo(h1), stA[j].w - bfhi(h1));
                *(uint2*)(smem + nb * TILEB + swoff(r, kq * 2))      = make_uint2(h0, h1);
                *(uint2*)(smem + nb * TILEB + swoff(r, 64 + kq * 2)) = make_uint2(l0, l1);
                h0 = packbf(stB[j].x, stB[j].y);
                h1 = packbf(stB[j].z, stB[j].w);
                l0 = packbf(stB[j].x - bflo(h0), stB[j].y - bfhi(h0));
                l1 = packbf(stB[j].z - bflo(h1), stB[j].w - bfhi(h1));
                *(uint2*)(smem + (2 + nb) * TILEB + swoff(r, kq * 2))      = make_uint2(h0, h1);
                *(uint2*)(smem + (2 + nb) * TILEB + swoff(r, 64 + kq * 2)) = make_uint2(l0, l1);
            }
        }
        __syncthreads();
    }

    // epilogue: d-frag -> global. d0,d1: row lane/4, cols 2*(lane%4)+{0,1}; d2,d3: row+8.
    #pragma unroll
    for (int mt = 0; mt < 4; mt++) {
        #pragma unroll
        for (int nt = 0; nt < 4; nt++) {
            int row = row0 + m0 + mt * 16 + (lane >> 2);
            int col = col0 + n0 + nt * 8 + (lane & 3) * 2;
            if (row < NR)
                *(float2*)(C + (size_t)row * KO + col) = make_float2(d[mt][nt][0], d[mt][nt][1]);
            if (row + 8 < NR)
                *(float2*)(C + (size_t)(row + 8) * KO + col) = make_float2(d[mt][nt][2], d[mt][nt][3]);
        }
    }
}

// ---------------- per-node attention scores ----------------------------------
__global__ void scores_k(const float* __restrict__ h,
                         const float* __restrict__ a_s, const float* __restrict__ a_d,
                         float* __restrict__ ss, float* __restrict__ sd,
                         int heads, int C)
{
    int n = blockIdx.x;
    int w = threadIdx.x >> 5, lane = threadIdx.x & 31;
    const float* hp = h + ((size_t)n * heads + w) * C;
    float s1 = 0.f, s2 = 0.f;
    for (int c = lane * 4; c < C; c += 128) {
        float4 hv = *(const float4*)(hp + c);
        float4 av = *(const float4*)(a_s + w * C + c);
        float4 dv = *(const float4*)(a_d + w * C + c);
        s1 += hv.x * av.x + hv.y * av.y + hv.z * av.z + hv.w * av.w;
        s2 += hv.x * dv.x + hv.y * dv.y + hv.z * dv.z + hv.w * dv.w;
    }
    #pragma unroll
    for (int o = 16; o; o >>= 1) {
        s1 += __shfl_xor_sync(0xffffffffu, s1, o);
        s2 += __shfl_xor_sync(0xffffffffu, s2, o);
    }
    if (lane == 0) { ss[n * heads + w] = s1; sd[n * heads + w] = s2; }
}

// ---------------- CSR aggregation: softmax + gather-reduce + bias ------------
__global__ void agg_k(const float* __restrict__ hmat,
                      const float* __restrict__ ss, const float* __restrict__ sd,
                      const float* __restrict__ bias, float* __restrict__ out,
                      int heads, int C, int applyLrelu)
{
    __shared__ float s_p[SMAX * NHEADS];
    __shared__ int   s_src[SMAX];
    __shared__ float s_mx[NHEADS], s_den[NHEADS];

    int n = blockIdx.x;
    int tid = threadIdx.x;
    int row0 = g_row[n];
    int deg = g_row[n + 1] - row0;

    int degc = deg < SMAX ? deg : SMAX;
    for (int i = tid; i < degc; i += blockDim.x) s_src[i] = g_srcs[row0 + i];
    __syncthreads();

    int w = tid >> 5, lane = tid & 31;
    if (w < heads) {
        float sdv = sd[n * heads + w];
        float mx = -3.4e38f;
        for (int i = lane; i < deg; i += 32) {
            int s = (i < SMAX) ? s_src[i] : g_srcs[row0 + i];
            float e = lrelu(ss[s * heads + w] + sdv);
            if (i < SMAX) s_p[i * heads + w] = e;
            mx = fmaxf(mx, e);
        }
        #pragma unroll
        for (int o = 16; o; o >>= 1) mx = fmaxf(mx, __shfl_xor_sync(0xffffffffu, mx, o));
        float den = 0.f;
        for (int i = lane; i < deg; i += 32) {
            float e = (i < SMAX) ? s_p[i * heads + w]
                                 : lrelu(ss[g_srcs[row0 + i] * heads + w] + sdv);
            float p = __expf(e - mx);
            if (i < SMAX) s_p[i * heads + w] = p;
            den += p;
        }
        #pragma unroll
        for (int o = 16; o; o >>= 1) den += __shfl_xor_sync(0xffffffffu, den, o);
        if (lane == 0) { s_mx[w] = mx; s_den[w] = den; }
    }
    __syncthreads();

    int cpq = C >> 2;
    int h = tid / cpq;
    int cq = tid - h * cpq;
    float mx = s_mx[h];
    float inv = 1.f / (s_den[h] + 1e-16f);
    float sdv = sd[n * heads + h];
    float4 acc = make_float4(0.f, 0.f, 0.f, 0.f);
    for (int i = 0; i < deg; i++) {
        int s = (i < SMAX) ? s_src[i] : g_srcs[row0 + i];
        float p = (i < SMAX) ? s_p[i * heads + h]
                             : __expf(lrelu(ss[s * heads + h] + sdv) - mx);
        float a = p * inv;
        float4 v = *(const float4*)(hmat + ((size_t)s * heads + h) * C + cq * 4);
        acc.x += v.x * a; acc.y += v.y * a; acc.z += v.z * a; acc.w += v.w * a;
    }
    int j = h * C + cq * 4;
    float4 bb = *(const float4*)(bias + j);
    acc.x += bb.x; acc.y += bb.y; acc.z += bb.z; acc.w += bb.w;
    if (applyLrelu) {
        acc.x = lrelu(acc.x); acc.y = lrelu(acc.y);
        acc.z = lrelu(acc.z); acc.w = lrelu(acc.w);
    }
    *(float4*)(out + (size_t)n * heads * C + j) = acc;
}

// ---------------- batchnorm --------------------------------------------------
__global__ void bn_stats_k(const float* __restrict__ x, float* __restrict__ bn)
{
    float ls0 = 0.f, ls1 = 0.f, lq0 = 0.f, lq1 = 0.f;
    int t = threadIdx.x;
    for (int n = blockIdx.x; n < NN; n += gridDim.x) {
        const float* r = x + (size_t)n * H1D;
        float v0 = r[t], v1 = r[t + 256];
        ls0 += v0; lq0 += v0 * v0;
        ls1 += v1; lq1 += v1 * v1;
    }
    atomicAdd(bn + t, ls0);             atomicAdd(bn + t + 256, ls1);
    atomicAdd(bn + 512 + t, lq0);       atomicAdd(bn + 512 + t + 256, lq1);
}
__global__ void bn_apply_k(float* __restrict__ x, const float* __restrict__ bn,
                           const float* __restrict__ gamma, const float* __restrict__ beta)
{
    int idx = blockIdx.x * blockDim.x + threadIdx.x;
    if (idx >= NN * H1D) return;
    int c = idx & 511;
    const float invN = 1.0f / NN;
    float mu = bn[c] * invN;
    float var = bn[512 + c] * invN - mu * mu;
    float v = gamma[c] * (x[idx] - mu) * rsqrtf(var + 1e-5f) + beta[c];
    x[idx] = lrelu(v);
}

// ---------------- pooling ----------------------------------------------------
__global__ void pool_acc_k(const float* __restrict__ h3, const int* __restrict__ batch,
                           float* __restrict__ out, float* __restrict__ cnt)
{
    int idx = blockIdx.x * blockDim.x + threadIdx.x;
    if (idx >= NN * OUTD) return;
    int n = idx >> 8, c = idx & 255;
    int b = batch[n];
    atomicAdd(out + b * OUTD + c, h3[idx]);
    if (c == 0) atomicAdd(cnt + b, 1.f);
}
__global__ void pool_div_k(float* __restrict__ out, const float* __restrict__ cnt)
{
    int i = blockIdx.x * blockDim.x + threadIdx.x;
    if (i >= BB * OUTD) return;
    float c = cnt[i >> 8];
    out[i] /= (c > 1.f ? c : 1.f);
}

// ---------------- host orchestration ----------------------------------------
static inline int ceil_div(int a, int b) { return (a + b - 1) / b; }

extern "C" void kernel_launch(void* const* d_in, const int* in_sizes, int n_in,
                              void* d_out, int out_size)
{
    const float* x      = (const float*)d_in[0];
    const int*   ei     = (const int*)  d_in[1];
    const int*   batch  = (const int*)  d_in[2];
    const float* W1     = (const float*)d_in[3];
    const float* asrc1  = (const float*)d_in[4];
    const float* adst1  = (const float*)d_in[5];
    const float* b1     = (const float*)d_in[6];
    const float* gamma1 = (const float*)d_in[7];
    const float* beta1  = (const float*)d_in[8];
    const float* W2     = (const float*)d_in[9];
    const float* asrc2  = (const float*)d_in[10];
    const float* adst2  = (const float*)d_in[11];
    const float* b2     = (const float*)d_in[12];
    const float* gamma2 = (const float*)d_in[13];
    const float* beta2  = (const float*)d_in[14];
    const float* W3     = (const float*)d_in[15];
    const float* asrc3  = (const float*)d_in[16];
    const float* adst3  = (const float*)d_in[17];
    const float* b3     = (const float*)d_in[18];
    float* out = (float*)d_out;

    float *hB, *featB, *wtB, *ssB, *sdB, *bnB, *cntB;
    int *degB;
    cudaGetSymbolAddress((void**)&hB,    g_h);
    cudaGetSymbolAddress((void**)&featB, g_feat);
    cudaGetSymbolAddress((void**)&wtB,   g_wt);
    cudaGetSymbolAddress((void**)&ssB,   g_ssrc);
    cudaGetSymbolAddress((void**)&sdB,   g_sdst);
    cudaGetSymbolAddress((void**)&bnB,   g_bn);
    cudaGetSymbolAddress((void**)&cntB,  g_cnt);
    cudaGetSymbolAddress((void**)&degB,  g_deg);

    cudaFuncSetAttribute(gemm_mma_k, cudaFuncAttributeMaxDynamicSharedMemorySize, GEMM_SMEM);

    int rowBlocks = ceil_div(NN, 128);

    // ---- CSR build ----
    cudaMemsetAsync(degB, 0, NN * sizeof(int));
    deg_k <<<ceil_div(ET, 256), 256>>>(ei);
    scan_k<<<1, 1024>>>();
    fill_k<<<ceil_div(ET, 256), 256>>>(ei);

    // ================= Layer 1: 768 -> 4x128 =================
    transpose_k<<<dim3(H1D / 32, IND / 32), dim3(32, 8)>>>(W1, wtB, IND, H1D);
    gemm_mma_k<<<dim3(H1D / 128, rowBlocks), 256, GEMM_SMEM>>>(x, wtB, hB, NN, IND, H1D);
    scores_k<<<NN, NHEADS * 32>>>(hB, asrc1, adst1, ssB, sdB, NHEADS, HIDC);
    agg_k<<<NN, NHEADS * (HIDC / 4)>>>(hB, ssB, sdB, b1, featB, NHEADS, HIDC, 0);
    cudaMemsetAsync(bnB, 0, 2 * H1D * sizeof(float));
    bn_stats_k<<<256, 256>>>(featB, bnB);
    bn_apply_k<<<ceil_div(NN * H1D, 256), 256>>>(featB, bnB, gamma1, beta1);

    // ================= Layer 2: 512 -> 4x128 =================
    transpose_k<<<dim3(H1D / 32, H1D / 32), dim3(32, 8)>>>(W2, wtB, H1D, H1D);
    gemm_mma_k<<<dim3(H1D / 128, rowBlocks), 256, GEMM_SMEM>>>(featB, wtB, hB, NN, H1D, H1D);
    scores_k<<<NN, NHEADS * 32>>>(hB, asrc2, adst2, ssB, sdB, NHEADS, HIDC);
    agg_k<<<NN, NHEADS * (HIDC / 4)>>>(hB, ssB, sdB, b2, featB, NHEADS, HIDC, 0);
    cudaMemsetAsync(bnB, 0, 2 * H1D * sizeof(float));
    bn_stats_k<<<256, 256>>>(featB, bnB);
    bn_apply_k<<<ceil_div(NN * H1D, 256), 256>>>(featB, bnB, gamma2, beta2);

    // ================= Layer 3: 512 -> 1x256 =================
    transpose_k<<<dim3(OUTD / 32, H1D / 32), dim3(32, 8)>>>(W3, wtB, H1D, OUTD);
    gemm_mma_k<<<dim3(OUTD / 128, rowBlocks), 256, GEMM_SMEM>>>(featB, wtB, hB, NN, H1D, OUTD);
    scores_k<<<NN, 32>>>(hB, asrc3, adst3, ssB, sdB, 1, OUTD);
    agg_k<<<NN, OUTD / 4>>>(hB, ssB, sdB, b3, featB, 1, OUTD, 1);

    // ================= Global mean pool =================
    cudaMemsetAsync(out, 0, (size_t)BB * OUTD * sizeof(float));
    cudaMemsetAsync(cntB, 0, BB * sizeof(float));
    pool_acc_k<<<ceil_div(NN * OUTD, 256), 256>>>(featB, batch, out, cntB);
    pool_div_k<<<ceil_div(BB * OUTD, 256), 256>>>(out, cntB);
}

// round 5
// speedup vs baseline: 3.0089x; 1.0810x over previous
#include <cuda_runtime.h>
#include <cuda_bf16.h>
#include <cstdint>
#include <cstddef>

#define NN    20000
#define EE    320000
#define ET    340000
#define BB    64
#define IND   768
#define H1D   512
#define NHEADS 4
#define HIDC  128
#define OUTD  256
#define SMAX  192

// ---------------- scratch (device globals) ----------------------------------
__device__ float g_h   [(size_t)NN * H1D];
__device__ float g_feat[(size_t)NN * H1D];
__device__ float g_wt  [(size_t)IND * H1D];
__device__ float g_ssrc[NN * NHEADS];
__device__ float g_sdst[NN * NHEADS];
__device__ float g_bn  [2 * H1D];
__device__ float g_cnt [BB];
__device__ int   g_deg [NN];
__device__ int   g_row [NN + 1];
__device__ int   g_cur [NN];
__device__ int   g_srcs[ET];

__device__ __forceinline__ float lrelu(float v) { return v > 0.f ? v : 0.2f * v; }

__device__ __forceinline__ uint32_t packbf(float x, float y) {
    uint32_t r;
    asm("cvt.rn.bf16x2.f32 %0, %1, %2;" : "=r"(r) : "f"(y), "f"(x));
    return r;
}
__device__ __forceinline__ float bflo(uint32_t u) {
    __nv_bfloat16 b = *reinterpret_cast<__nv_bfloat16*>(&u);
    return __bfloat162float(b);
}
__device__ __forceinline__ float bfhi(uint32_t u) {
    uint32_t h = u >> 16;
    __nv_bfloat16 b = *reinterpret_cast<__nv_bfloat16*>(&h);
    return __bfloat162float(b);
}

#define LDSM4(r0, r1, r2, r3, addr) \
    asm volatile("ldmatrix.sync.aligned.m8n8.x4.shared.b16 {%0,%1,%2,%3}, [%4];" \
        : "=r"(r0), "=r"(r1), "=r"(r2), "=r"(r3) : "r"(addr))

#define MMA_BF16(d, a, b) \
    asm volatile("mma.sync.aligned.m16n8k16.row.col.f32.bf16.bf16.f32 " \
        "{%0,%1,%2,%3}, {%4,%5,%6,%7}, {%8,%9}, {%0,%1,%2,%3};" \
        : "+f"((d)[0]), "+f"((d)[1]), "+f"((d)[2]), "+f"((d)[3]) \
        : "r"((a)[0]), "r"((a)[1]), "r"((a)[2]), "r"((a)[3]), "r"((b)[0]), "r"((b)[1]))

__device__ __forceinline__ uint32_t smem_u32(const void* p) {
    uint32_t a;
    asm("{ .reg .u64 t; cvta.to.shared.u64 t, %1; cvt.u32.u64 %0, t; }" : "=r"(a) : "l"(p));
    return a;
}

// ---------------- CSR build --------------------------------------------------
__global__ void deg_k(const int* __restrict__ ei) {
    int e = blockIdx.x * blockDim.x + threadIdx.x;
    if (e >= ET) return;
    int d = (e < EE) ? ei[EE + e] : (e - EE);
    atomicAdd(&g_deg[d], 1);
}
#define SCHK 20
__global__ __launch_bounds__(1024) void scan_k() {
    __shared__ int s[1024];
    int t = threadIdx.x;
    int base = t * SCHK;
    int local[SCHK];
    int sum = 0;
    #pragma unroll
    for (int i = 0; i < SCHK; i++) {
        int idx = base + i;
        int v = (idx < NN) ? g_deg[idx] : 0;
        local[i] = sum;
        sum += v;
    }
    s[t] = sum;
    __syncthreads();
    for (int off = 1; off < 1024; off <<= 1) {
        int v = (t >= off) ? s[t - off] : 0;
        __syncthreads();
        s[t] += v;
        __syncthreads();
    }
    int boff = (t > 0) ? s[t - 1] : 0;
    #pragma unroll
    for (int i = 0; i < SCHK; i++) {
        int idx = base + i;
        if (idx < NN) {
            int r = boff + local[i];
            g_row[idx] = r;
            g_cur[idx] = r;
        }
    }
    if (t == 1023) g_row[NN] = s[1023];
}
__global__ void fill_k(const int* __restrict__ ei) {
    int e = blockIdx.x * blockDim.x + threadIdx.x;
    if (e >= ET) return;
    int s, d;
    if (e < EE) { s = ei[e]; d = ei[EE + e]; } else { s = d = e - EE; }
    int p = atomicAdd(&g_cur[d], 1);
    g_srcs[p] = s;
}

// ---------------- weight transpose: W[M,K] -> WT[K,M] ------------------------
__global__ void transpose_k(const float* __restrict__ W, float* __restrict__ WT, int M, int K)
{
    __shared__ float t[32][33];
    int x = blockIdx.x * 32 + threadIdx.x;
    int y0 = blockIdx.y * 32;
    for (int i = threadIdx.y; i < 32; i += 8)
        t[i][threadIdx.x] = W[(size_t)(y0 + i) * K + x];
    __syncthreads();
    int xo = y0 + threadIdx.x;
    int yo0 = blockIdx.x * 32;
    for (int i = threadIdx.y; i < 32; i += 8)
        WT[(size_t)(yo0 + i) * M + xo] = t[threadIdx.x][i];
}

// ---------------- bf16-split tensor-core GEMM --------------------------------
#define TILEB 16384
#define GEMM_SMEM (4 * TILEB)

__device__ __forceinline__ uint32_t swoff(int r, int cByte) {
    return (uint32_t)(r * 128 + (cByte ^ ((r & 7) << 4)));
}

__global__ __launch_bounds__(256, 1) void gemm_mma_k(
    const float* __restrict__ A, const float* __restrict__ WT,
    float* __restrict__ C, int NR, int KD, int KO)
{
    extern __shared__ char smem[];
    uint32_t sA = smem_u32(smem);
    uint32_t sB = sA + 2 * TILEB;
    const int tid = threadIdx.x;
    const int wid = tid >> 5, lane = tid & 31;
    const int row0 = blockIdx.y * 128, col0 = blockIdx.x * 128;
    const int m0 = (wid >> 2) * 64, n0 = (wid & 3) * 32;

    float4 stA[4], stB[4];
    const int nc = KD / 32;

    const int arow = (lane & 15);
    const int acb  = ((lane >> 4) & 1) * 16;
    const int brow = (lane & 7) + ((lane >> 4) & 1) * 8;
    const int bcb  = ((lane >> 3) & 1) * 16;

    float d[4][4][4];
    #pragma unroll
    for (int i = 0; i < 4; i++)
        #pragma unroll
        for (int j = 0; j < 4; j++)
            { d[i][j][0] = 0.f; d[i][j][1] = 0.f; d[i][j][2] = 0.f; d[i][j][3] = 0.f; }

    #pragma unroll
    for (int j = 0; j < 4; j++) {
        int q = tid + j * 256;
        int r = q >> 3, kq = (q & 7) * 4;
        int gr = row0 + r;
        stA[j] = make_float4(0.f, 0.f, 0.f, 0.f);
        if (gr < NR) stA[j] = *(const float4*)(A + (size_t)gr * KD + kq);
        stB[j] = *(const float4*)(WT + (size_t)(col0 + r) * KD + kq);
    }
    {
        #pragma unroll
        for (int j = 0; j < 4; j++) {
            int q = tid + j * 256;
            int r = q >> 3, kq = (q & 7) * 4;
            uint32_t h0 = packbf(stA[j].x, stA[j].y);
            uint32_t h1 = packbf(stA[j].z, stA[j].w);
            uint32_t l0 = packbf(stA[j].x - bflo(h0), stA[j].y - bfhi(h0));
            uint32_t l1 = packbf(stA[j].z - bflo(h1), stA[j].w - bfhi(h1));
            *(uint2*)(smem + swoff(r, kq * 2))      = make_uint2(h0, h1);
            *(uint2*)(smem + swoff(r, 64 + kq * 2)) = make_uint2(l0, l1);
            h0 = packbf(stB[j].x, stB[j].y);
            h1 = packbf(stB[j].z, stB[j].w);
            l0 = packbf(stB[j].x - bflo(h0), stB[j].y - bfhi(h0));
            l1 = packbf(stB[j].z - bflo(h1), stB[j].w - bfhi(h1));
            *(uint2*)(smem + 2 * TILEB + swoff(r, kq * 2))      = make_uint2(h0, h1);
            *(uint2*)(smem + 2 * TILEB + swoff(r, 64 + kq * 2)) = make_uint2(l0, l1);
        }
    }
    __syncthreads();

    for (int c = 0; c < nc; c++) {
        int buf = c & 1;
        uint32_t aBase = sA + buf * TILEB;
        uint32_t bBase = sB + buf * TILEB;
        bool more = (c + 1 < nc);

        if (more) {
            int k0 = (c + 1) * 32;
            #pragma unroll
            for (int j = 0; j < 4; j++) {
                int q = tid + j * 256;
                int r = q >> 3, kq = (q & 7) * 4;
                int gr = row0 + r;
                stA[j] = make_float4(0.f, 0.f, 0.f, 0.f);
                if (gr < NR) stA[j] = *(const float4*)(A + (size_t)gr * KD + k0 + kq);
                stB[j] = *(const float4*)(WT + (size_t)(col0 + r) * KD + k0 + kq);
            }
        }

        #pragma unroll
        for (int s = 0; s < 2; s++) {
            uint32_t Ah[4][4], Al[4][4], Bh[4][2], Bl[4][2];
            #pragma unroll
            for (int mt = 0; mt < 4; mt++) {
                int r = m0 + mt * 16 + arow;
                LDSM4(Ah[mt][0], Ah[mt][1], Ah[mt][2], Ah[mt][3],
                      aBase + swoff(r, s * 32 + acb));
                LDSM4(Al[mt][0], Al[mt][1], Al[mt][2], Al[mt][3],
                      aBase + swoff(r, 64 + s * 32 + acb));
            }
            #pragma unroll
            for (int p = 0; p < 2; p++) {
                int r = n0 + p * 16 + brow;
                LDSM4(Bh[2 * p][0], Bh[2 * p][1], Bh[2 * p + 1][0], Bh[2 * p + 1][1],
                      bBase + swoff(r, s * 32 + bcb));
                LDSM4(Bl[2 * p][0], Bl[2 * p][1], Bl[2 * p + 1][0], Bl[2 * p + 1][1],
                      bBase + swoff(r, 64 + s * 32 + bcb));
            }
            #pragma unroll
            for (int mt = 0; mt < 4; mt++)
                #pragma unroll
                for (int nt = 0; nt < 4; nt++) {
                    MMA_BF16(d[mt][nt], Ah[mt], Bh[nt]);
                    MMA_BF16(d[mt][nt], Ah[mt], Bl[nt]);
                    MMA_BF16(d[mt][nt], Al[mt], Bh[nt]);
                }
        }

        if (more) {
            int nb = buf ^ 1;
            #pragma unroll
            for (int j = 0; j < 4; j++) {
                int q = tid + j * 256;
                int r = q >> 3, kq = (q & 7) * 4;
                uint32_t h0 = packbf(stA[j].x, stA[j].y);
                uint32_t h1 = packbf(stA[j].z, stA[j].w);
                uint32_t l0 = packbf(stA[j].x - bflo(h0), stA[j].y - bfhi(h0));
                uint32_t l1 = packbf(stA[j].z - bflo(h1), stA[j].w - bfhi(h1));
                *(uint2*)(smem + nb * TILEB + swoff(r, kq * 2))      = make_uint2(h0, h1);
                *(uint2*)(smem + nb * TILEB + swoff(r, 64 + kq * 2)) = make_uint2(l0, l1);
                h0 = packbf(stB[j].x, stB[j].y);
                h1 = packbf(stB[j].z, stB[j].w);
                l0 = packbf(stB[j].x - bflo(h0), stB[j].y - bfhi(h0));
                l1 = packbf(stB[j].z - bflo(h1), stB[j].w - bfhi(h1));
                *(uint2*)(smem + (2 + nb) * TILEB + swoff(r, kq * 2))      = make_uint2(h0, h1);
                *(uint2*)(smem + (2 + nb) * TILEB + swoff(r, 64 + kq * 2)) = make_uint2(l0, l1);
            }
        }
        __syncthreads();
    }

    #pragma unroll
    for (int mt = 0; mt < 4; mt++) {
        #pragma unroll
        for (int nt = 0; nt < 4; nt++) {
            int row = row0 + m0 + mt * 16 + (lane >> 2);
            int col = col0 + n0 + nt * 8 + (lane & 3) * 2;
            if (row < NR)
                *(float2*)(C + (size_t)row * KO + col) = make_float2(d[mt][nt][0], d[mt][nt][1]);
            if (row + 8 < NR)
                *(float2*)(C + (size_t)(row + 8) * KO + col) = make_float2(d[mt][nt][2], d[mt][nt][3]);
        }
    }
}

// ---------------- per-node attention scores ----------------------------------
__global__ void scores_k(const float* __restrict__ h,
                         const float* __restrict__ a_s, const float* __restrict__ a_d,
                         float* __restrict__ ss, float* __restrict__ sd,
                         int heads, int C)
{
    int n = blockIdx.x;
    int w = threadIdx.x >> 5, lane = threadIdx.x & 31;
    const float* hp = h + ((size_t)n * heads + w) * C;
    float s1 = 0.f, s2 = 0.f;
    for (int c = lane * 4; c < C; c += 128) {
        float4 hv = *(const float4*)(hp + c);
        float4 av = *(const float4*)(a_s + w * C + c);
        float4 dv = *(const float4*)(a_d + w * C + c);
        s1 += hv.x * av.x + hv.y * av.y + hv.z * av.z + hv.w * av.w;
        s2 += hv.x * dv.x + hv.y * dv.y + hv.z * dv.z + hv.w * dv.w;
    }
    #pragma unroll
    for (int o = 16; o; o >>= 1) {
        s1 += __shfl_xor_sync(0xffffffffu, s1, o);
        s2 += __shfl_xor_sync(0xffffffffu, s2, o);
    }
    if (lane == 0) { ss[n * heads + w] = s1; sd[n * heads + w] = s2; }
}

// ---------------- CSR aggregation: softmax + gather-reduce + bias ------------
__global__ void agg_k(const float* __restrict__ hmat,
                      const float* __restrict__ ss, const float* __restrict__ sd,
                      const float* __restrict__ bias, float* __restrict__ out,
                      int heads, int C, int applyLrelu)
{
    __shared__ float s_p[SMAX * NHEADS];
    __shared__ int   s_src[SMAX];
    __shared__ float s_mx[NHEADS], s_den[NHEADS];

    int n = blockIdx.x;
    int tid = threadIdx.x;
    int row0 = g_row[n];
    int deg = g_row[n + 1] - row0;

    int degc = deg < SMAX ? deg : SMAX;
    for (int i = tid; i < degc; i += blockDim.x) s_src[i] = g_srcs[row0 + i];
    __syncthreads();

    int w = tid >> 5, lane = tid & 31;
    if (w < heads) {
        float sdv = sd[n * heads + w];
        float mx = -3.4e38f;
        for (int i = lane; i < deg; i += 32) {
            int s = (i < SMAX) ? s_src[i] : g_srcs[row0 + i];
            float e = lrelu(ss[s * heads + w] + sdv);
            if (i < SMAX) s_p[i * heads + w] = e;
            mx = fmaxf(mx, e);
        }
        #pragma unroll
        for (int o = 16; o; o >>= 1) mx = fmaxf(mx, __shfl_xor_sync(0xffffffffu, mx, o));
        float den = 0.f;
        for (int i = lane; i < deg; i += 32) {
            float e = (i < SMAX) ? s_p[i * heads + w]
                                 : lrelu(ss[g_srcs[row0 + i] * heads + w] + sdv);
            float p = __expf(e - mx);
            if (i < SMAX) s_p[i * heads + w] = p;
            den += p;
        }
        #pragma unroll
        for (int o = 16; o; o >>= 1) den += __shfl_xor_sync(0xffffffffu, den, o);
        if (lane == 0) { s_mx[w] = mx; s_den[w] = den; }
    }
    __syncthreads();

    int cpq = C >> 2;
    int h = tid / cpq;
    int cq = tid - h * cpq;
    float inv = 1.f / (s_den[h] + 1e-16f);
    float4 acc = make_float4(0.f, 0.f, 0.f, 0.f);

    if (deg <= SMAX) {
        // fast path: 4-way unrolled, MLP=4 gathers in flight
        const size_t hstr = (size_t)heads * C;
        const int coff = h * C + cq * 4;
        int i = 0;
        for (; i + 4 <= deg; i += 4) {
            int s0 = s_src[i + 0], s1 = s_src[i + 1];
            int s2 = s_src[i + 2], s3 = s_src[i + 3];
            float p0 = s_p[(i + 0) * heads + h], p1 = s_p[(i + 1) * heads + h];
            float p2 = s_p[(i + 2) * heads + h], p3 = s_p[(i + 3) * heads + h];
            float4 v0 = *(const float4*)(hmat + (size_t)s0 * hstr + coff);
            float4 v1 = *(const float4*)(hmat + (size_t)s1 * hstr + coff);
            float4 v2 = *(const float4*)(hmat + (size_t)s2 * hstr + coff);
            float4 v3 = *(const float4*)(hmat + (size_t)s3 * hstr + coff);
            acc.x += v0.x * p0 + v1.x * p1 + v2.x * p2 + v3.x * p3;
            acc.y += v0.y * p0 + v1.y * p1 + v2.y * p2 + v3.y * p3;
            acc.z += v0.z * p0 + v1.z * p1 + v2.z * p2 + v3.z * p3;
            acc.w += v0.w * p0 + v1.w * p1 + v2.w * p2 + v3.w * p3;
        }
        for (; i < deg; i++) {
            int s = s_src[i];
            float p = s_p[i * heads + h];
            float4 v = *(const float4*)(hmat + (size_t)s * hstr + coff);
            acc.x += v.x * p; acc.y += v.y * p; acc.z += v.z * p; acc.w += v.w * p;
        }
    } else {
        float mx = s_mx[h];
        float sdv = sd[n * heads + h];
        for (int i = 0; i < deg; i++) {
            int s = (i < SMAX) ? s_src[i] : g_srcs[row0 + i];
            float p = (i < SMAX) ? s_p[i * heads + h]
                                 : __expf(lrelu(ss[s * heads + h] + sdv) - mx);
            float4 v = *(const float4*)(hmat + ((size_t)s * heads + h) * C + cq * 4);
            acc.x += v.x * p; acc.y += v.y * p; acc.z += v.z * p; acc.w += v.w * p;
        }
    }

    acc.x *= inv; acc.y *= inv; acc.z *= inv; acc.w *= inv;
    int j = h * C + cq * 4;
    float4 bb = *(const float4*)(bias + j);
    acc.x += bb.x; acc.y += bb.y; acc.z += bb.z; acc.w += bb.w;
    if (applyLrelu) {
        acc.x = lrelu(acc.x); acc.y = lrelu(acc.y);
        acc.z = lrelu(acc.z); acc.w = lrelu(acc.w);
    }
    *(float4*)(out + (size_t)n * heads * C + j) = acc;
}

// ---------------- batchnorm --------------------------------------------------
__global__ void bn_stats_k(const float* __restrict__ x, float* __restrict__ bn)
{
    float ls0 = 0.f, ls1 = 0.f, lq0 = 0.f, lq1 = 0.f;
    int t = threadIdx.x;
    for (int n = blockIdx.x; n < NN; n += gridDim.x) {
        const float* r = x + (size_t)n * H1D;
        float v0 = r[t], v1 = r[t + 256];
        ls0 += v0; lq0 += v0 * v0;
        ls1 += v1; lq1 += v1 * v1;
    }
    atomicAdd(bn + t, ls0);             atomicAdd(bn + t + 256, ls1);
    atomicAdd(bn + 512 + t, lq0);       atomicAdd(bn + 512 + t + 256, lq1);
}
__global__ void bn_apply_k(float* __restrict__ x, const float* __restrict__ bn,
                           const float* __restrict__ gamma, const float* __restrict__ beta)
{
    int idx = blockIdx.x * blockDim.x + threadIdx.x;
    if (idx >= NN * H1D) return;
    int c = idx & 511;
    const float invN = 1.0f / NN;
    float mu = bn[c] * invN;
    float var = bn[512 + c] * invN - mu * mu;
    float v = gamma[c] * (x[idx] - mu) * rsqrtf(var + 1e-5f) + beta[c];
    x[idx] = lrelu(v);
}

// ---------------- pooling ----------------------------------------------------
// batch sorted: 8 nodes per thread, flush on graph change -> atomics / 8
#define PCH 8
__global__ void pool_acc_k(const float* __restrict__ h3, const int* __restrict__ batch,
                           float* __restrict__ out, float* __restrict__ cnt)
{
    int c = threadIdx.x;                 // 0..255
    int n0 = blockIdx.x * PCH;
    if (n0 >= NN) return;
    float acc = 0.f, ac = 0.f;
    int curb = batch[n0];
    #pragma unroll
    for (int k = 0; k < PCH; k++) {
        int n = n0 + k;
        if (n >= NN) break;
        int b = batch[n];
        if (b != curb) {
            atomicAdd(out + curb * OUTD + c, acc);
            if (c == 0) atomicAdd(cnt + curb, ac);
            acc = 0.f; ac = 0.f; curb = b;
        }
        acc += h3[(size_t)n * OUTD + c];
        ac += 1.f;
    }
    atomicAdd(out + curb * OUTD + c, acc);
    if (c == 0) atomicAdd(cnt + curb, ac);
}
__global__ void pool_div_k(float* __restrict__ out, const float* __restrict__ cnt)
{
    int i = blockIdx.x * blockDim.x + threadIdx.x;
    if (i >= BB * OUTD) return;
    float c = cnt[i >> 8];
    out[i] /= (c > 1.f ? c : 1.f);
}

// ---------------- host orchestration ----------------------------------------
static inline int ceil_div(int a, int b) { return (a + b - 1) / b; }

extern "C" void kernel_launch(void* const* d_in, const int* in_sizes, int n_in,
                              void* d_out, int out_size)
{
    const float* x      = (const float*)d_in[0];
    const int*   ei     = (const int*)  d_in[1];
    const int*   batch  = (const int*)  d_in[2];
    const float* W1     = (const float*)d_in[3];
    const float* asrc1  = (const float*)d_in[4];
    const float* adst1  = (const float*)d_in[5];
    const float* b1     = (const float*)d_in[6];
    const float* gamma1 = (const float*)d_in[7];
    const float* beta1  = (const float*)d_in[8];
    const float* W2     = (const float*)d_in[9];
    const float* asrc2  = (const float*)d_in[10];
    const float* adst2  = (const float*)d_in[11];
    const float* b2     = (const float*)d_in[12];
    const float* gamma2 = (const float*)d_in[13];
    const float* beta2  = (const float*)d_in[14];
    const float* W3     = (const float*)d_in[15];
    const float* asrc3  = (const float*)d_in[16];
    const float* adst3  = (const float*)d_in[17];
    const float* b3     = (const float*)d_in[18];
    float* out = (float*)d_out;

    float *hB, *featB, *wtB, *ssB, *sdB, *bnB, *cntB;
    int *degB;
    cudaGetSymbolAddress((void**)&hB,    g_h);
    cudaGetSymbolAddress((void**)&featB, g_feat);
    cudaGetSymbolAddress((void**)&wtB,   g_wt);
    cudaGetSymbolAddress((void**)&ssB,   g_ssrc);
    cudaGetSymbolAddress((void**)&sdB,   g_sdst);
    cudaGetSymbolAddress((void**)&bnB,   g_bn);
    cudaGetSymbolAddress((void**)&cntB,  g_cnt);
    cudaGetSymbolAddress((void**)&degB,  g_deg);

    cudaFuncSetAttribute(gemm_mma_k, cudaFuncAttributeMaxDynamicSharedMemorySize, GEMM_SMEM);

    int rowBlocks = ceil_div(NN, 128);

    // ---- CSR build ----
    cudaMemsetAsync(degB, 0, NN * sizeof(int));
    deg_k <<<ceil_div(ET, 256), 256>>>(ei);
    scan_k<<<1, 1024>>>();
    fill_k<<<ceil_div(ET, 256), 256>>>(ei);

    // ================= Layer 1 =================
    transpose_k<<<dim3(H1D / 32, IND / 32), dim3(32, 8)>>>(W1, wtB, IND, H1D);
    gemm_mma_k<<<dim3(H1D / 128, rowBlocks), 256, GEMM_SMEM>>>(x, wtB, hB, NN, IND, H1D);
    scores_k<<<NN, NHEADS * 32>>>(hB, asrc1, adst1, ssB, sdB, NHEADS, HIDC);
    agg_k<<<NN, NHEADS * (HIDC / 4)>>>(hB, ssB, sdB, b1, featB, NHEADS, HIDC, 0);
    cudaMemsetAsync(bnB, 0, 2 * H1D * sizeof(float));
    bn_stats_k<<<256, 256>>>(featB, bnB);
    bn_apply_k<<<ceil_div(NN * H1D, 256), 256>>>(featB, bnB, gamma1, beta1);

    // ================= Layer 2 =================
    transpose_k<<<dim3(H1D / 32, H1D / 32), dim3(32, 8)>>>(W2, wtB, H1D, H1D);
    gemm_mma_k<<<dim3(H1D / 128, rowBlocks), 256, GEMM_SMEM>>>(featB, wtB, hB, NN, H1D, H1D);
    scores_k<<<NN, NHEADS * 32>>>(hB, asrc2, adst2, ssB, sdB, NHEADS, HIDC);
    agg_k<<<NN, NHEADS * (HIDC / 4)>>>(hB, ssB, sdB, b2, featB, NHEADS, HIDC, 0);
    cudaMemsetAsync(bnB, 0, 2 * H1D * sizeof(float));
    bn_stats_k<<<256, 256>>>(featB, bnB);
    bn_apply_k<<<ceil_div(NN * H1D, 256), 256>>>(featB, bnB, gamma2, beta2);

    // ================= Layer 3 =================
    transpose_k<<<dim3(OUTD / 32, H1D / 32), dim3(32, 8)>>>(W3, wtB, H1D, OUTD);
    gemm_mma_k<<<dim3(OUTD / 128, rowBlocks), 256, GEMM_SMEM>>>(featB, wtB, hB, NN, H1D, OUTD);
    scores_k<<<NN, 32>>>(hB, asrc3, adst3, ssB, sdB, 1, OUTD);
    agg_k<<<NN, OUTD / 4>>>(hB, ssB, sdB, b3, featB, 1, OUTD, 1);

    // ================= Global mean pool =================
    cudaMemsetAsync(out, 0, (size_t)BB * OUTD * sizeof(float));
    cudaMemsetAsync(cntB, 0, BB * sizeof(float));
    pool_acc_k<<<ceil_div(NN, PCH), OUTD>>>(featB, batch, out, cntB);
    pool_div_k<<<ceil_div(BB * OUTD, 256), 256>>>(out, cntB);
}

// round 6
// speedup vs baseline: 3.1287x; 1.0398x over previous
#include <cuda_runtime.h>
#include <cuda_bf16.h>
#include <cstdint>
#include <cstddef>

#define NN    20000
#define EE    320000
#define ET    340000
#define BB    64
#define IND   768
#define H1D   512
#define NHEADS 4
#define HIDC  128
#define OUTD  256
#define SMAX  192

// ---------------- scratch (device globals) ----------------------------------
__device__ float g_h   [(size_t)NN * H1D];
__device__ float g_feat[(size_t)NN * H1D];
__device__ float g_wt  [(size_t)IND * H1D];
__device__ float g_ssrc[NN * NHEADS];
__device__ float g_sdst[NN * NHEADS];
__device__ float g_bn  [2 * H1D];
__device__ float g_cnt [BB];
__device__ int   g_deg [NN];
__device__ int   g_row [NN + 1];
__device__ int   g_cur [NN];
__device__ int   g_srcs[ET];

__device__ __forceinline__ float lrelu(float v) { return v > 0.f ? v : 0.2f * v; }

__device__ __forceinline__ uint32_t packbf(float x, float y) {
    uint32_t r;
    asm("cvt.rn.bf16x2.f32 %0, %1, %2;" : "=r"(r) : "f"(y), "f"(x));
    return r;
}
__device__ __forceinline__ float bflo(uint32_t u) {
    __nv_bfloat16 b = *reinterpret_cast<__nv_bfloat16*>(&u);
    return __bfloat162float(b);
}
__device__ __forceinline__ float bfhi(uint32_t u) {
    uint32_t h = u >> 16;
    __nv_bfloat16 b = *reinterpret_cast<__nv_bfloat16*>(&h);
    return __bfloat162float(b);
}

#define LDSM4(r0, r1, r2, r3, addr) \
    asm volatile("ldmatrix.sync.aligned.m8n8.x4.shared.b16 {%0,%1,%2,%3}, [%4];" \
        : "=r"(r0), "=r"(r1), "=r"(r2), "=r"(r3) : "r"(addr))

#define MMA_BF16(d, a, b) \
    asm volatile("mma.sync.aligned.m16n8k16.row.col.f32.bf16.bf16.f32 " \
        "{%0,%1,%2,%3}, {%4,%5,%6,%7}, {%8,%9}, {%0,%1,%2,%3};" \
        : "+f"((d)[0]), "+f"((d)[1]), "+f"((d)[2]), "+f"((d)[3]) \
        : "r"((a)[0]), "r"((a)[1]), "r"((a)[2]), "r"((a)[3]), "r"((b)[0]), "r"((b)[1]))

__device__ __forceinline__ uint32_t smem_u32(const void* p) {
    uint32_t a;
    asm("{ .reg .u64 t; cvta.to.shared.u64 t, %1; cvt.u32.u64 %0, t; }" : "=r"(a) : "l"(p));
    return a;
}

// ---------------- CSR build --------------------------------------------------
__global__ void deg_k(const int* __restrict__ ei) {
    int e = blockIdx.x * blockDim.x + threadIdx.x;
    if (e >= ET) return;
    int d = (e < EE) ? ei[EE + e] : (e - EE);
    atomicAdd(&g_deg[d], 1);
}
#define SCHK 20
__global__ __launch_bounds__(1024) void scan_k() {
    __shared__ int s[1024];
    int t = threadIdx.x;
    int base = t * SCHK;
    int local[SCHK];
    int sum = 0;
    #pragma unroll
    for (int i = 0; i < SCHK; i++) {
        int idx = base + i;
        int v = (idx < NN) ? g_deg[idx] : 0;
        local[i] = sum;
        sum += v;
    }
    s[t] = sum;
    __syncthreads();
    for (int off = 1; off < 1024; off <<= 1) {
        int v = (t >= off) ? s[t - off] : 0;
        __syncthreads();
        s[t] += v;
        __syncthreads();
    }
    int boff = (t > 0) ? s[t - 1] : 0;
    #pragma unroll
    for (int i = 0; i < SCHK; i++) {
        int idx = base + i;
        if (idx < NN) {
            int r = boff + local[i];
            g_row[idx] = r;
            g_cur[idx] = r;
        }
    }
    if (t == 1023) g_row[NN] = s[1023];
}
__global__ void fill_k(const int* __restrict__ ei) {
    int e = blockIdx.x * blockDim.x + threadIdx.x;
    if (e >= ET) return;
    int s, d;
    if (e < EE) { s = ei[e]; d = ei[EE + e]; } else { s = d = e - EE; }
    int p = atomicAdd(&g_cur[d], 1);
    g_srcs[p] = s;
}

// ---------------- weight transpose: W[M,K] -> WT[K,M] ------------------------
__global__ void transpose_k(const float* __restrict__ W, float* __restrict__ WT, int M, int K)
{
    __shared__ float t[32][33];
    int x = blockIdx.x * 32 + threadIdx.x;
    int y0 = blockIdx.y * 32;
    for (int i = threadIdx.y; i < 32; i += 8)
        t[i][threadIdx.x] = W[(size_t)(y0 + i) * K + x];
    __syncthreads();
    int xo = y0 + threadIdx.x;
    int yo0 = blockIdx.x * 32;
    for (int i = threadIdx.y; i < 32; i += 8)
        WT[(size_t)(yo0 + i) * M + xo] = t[threadIdx.x][i];
}

// ---------------- bf16-split tensor-core GEMM + fused attention scores -------
// C[NR,KO] = A[NR,KD] * W[KD,KO]. Also emits per-row scores against a_s/a_d
// over this CTA's 128-col block: head = col0/headC; store if headC==128,
// atomicAdd (zeroed buffers) if headC>128.
#define TILEB 16384
#define GEMM_SMEM (4 * TILEB)

__device__ __forceinline__ uint32_t swoff(int r, int cByte) {
    return (uint32_t)(r * 128 + (cByte ^ ((r & 7) << 4)));
}

__global__ __launch_bounds__(256, 1) void gemm_mma_k(
    const float* __restrict__ A, const float* __restrict__ WT,
    float* __restrict__ C, int NR, int KD, int KO,
    const float* __restrict__ a_s, const float* __restrict__ a_d,
    float* __restrict__ ss, float* __restrict__ sd,
    int hstr, int headC)
{
    extern __shared__ char smem[];
    uint32_t sA = smem_u32(smem);
    uint32_t sB = sA + 2 * TILEB;
    const int tid = threadIdx.x;
    const int wid = tid >> 5, lane = tid & 31;
    const int row0 = blockIdx.y * 128, col0 = blockIdx.x * 128;
    const int m0 = (wid >> 2) * 64, n0 = (wid & 3) * 32;

    float4 stA[4], stB[4];
    const int nc = KD / 32;

    const int arow = (lane & 15);
    const int acb  = ((lane >> 4) & 1) * 16;
    const int brow = (lane & 7) + ((lane >> 4) & 1) * 8;
    const int bcb  = ((lane >> 3) & 1) * 16;

    float d[4][4][4];
    #pragma unroll
    for (int i = 0; i < 4; i++)
        #pragma unroll
        for (int j = 0; j < 4; j++)
            { d[i][j][0] = 0.f; d[i][j][1] = 0.f; d[i][j][2] = 0.f; d[i][j][3] = 0.f; }

    #pragma unroll
    for (int j = 0; j < 4; j++) {
        int q = tid + j * 256;
        int r = q >> 3, kq = (q & 7) * 4;
        int gr = row0 + r;
        stA[j] = make_float4(0.f, 0.f, 0.f, 0.f);
        if (gr < NR) stA[j] = *(const float4*)(A + (size_t)gr * KD + kq);
        stB[j] = *(const float4*)(WT + (size_t)(col0 + r) * KD + kq);
    }
    {
        #pragma unroll
        for (int j = 0; j < 4; j++) {
            int q = tid + j * 256;
            int r = q >> 3, kq = (q & 7) * 4;
            uint32_t h0 = packbf(stA[j].x, stA[j].y);
            uint32_t h1 = packbf(stA[j].z, stA[j].w);
            uint32_t l0 = packbf(stA[j].x - bflo(h0), stA[j].y - bfhi(h0));
            uint32_t l1 = packbf(stA[j].z - bflo(h1), stA[j].w - bfhi(h1));
            *(uint2*)(smem + swoff(r, kq * 2))      = make_uint2(h0, h1);
            *(uint2*)(smem + swoff(r, 64 + kq * 2)) = make_uint2(l0, l1);
            h0 = packbf(stB[j].x, stB[j].y);
            h1 = packbf(stB[j].z, stB[j].w);
            l0 = packbf(stB[j].x - bflo(h0), stB[j].y - bfhi(h0));
            l1 = packbf(stB[j].z - bflo(h1), stB[j].w - bfhi(h1));
            *(uint2*)(smem + 2 * TILEB + swoff(r, kq * 2))      = make_uint2(h0, h1);
            *(uint2*)(smem + 2 * TILEB + swoff(r, 64 + kq * 2)) = make_uint2(l0, l1);
        }
    }
    __syncthreads();

    for (int c = 0; c < nc; c++) {
        int buf = c & 1;
        uint32_t aBase = sA + buf * TILEB;
        uint32_t bBase = sB + buf * TILEB;
        bool more = (c + 1 < nc);

        if (more) {
            int k0 = (c + 1) * 32;
            #pragma unroll
            for (int j = 0; j < 4; j++) {
                int q = tid + j * 256;
                int r = q >> 3, kq = (q & 7) * 4;
                int gr = row0 + r;
                stA[j] = make_float4(0.f, 0.f, 0.f, 0.f);
                if (gr < NR) stA[j] = *(const float4*)(A + (size_t)gr * KD + k0 + kq);
                stB[j] = *(const float4*)(WT + (size_t)(col0 + r) * KD + k0 + kq);
            }
        }

        #pragma unroll
        for (int s = 0; s < 2; s++) {
            uint32_t Ah[4][4], Al[4][4], Bh[4][2], Bl[4][2];
            #pragma unroll
            for (int mt = 0; mt < 4; mt++) {
                int r = m0 + mt * 16 + arow;
                LDSM4(Ah[mt][0], Ah[mt][1], Ah[mt][2], Ah[mt][3],
                      aBase + swoff(r, s * 32 + acb));
                LDSM4(Al[mt][0], Al[mt][1], Al[mt][2], Al[mt][3],
                      aBase + swoff(r, 64 + s * 32 + acb));
            }
            #pragma unroll
            for (int p = 0; p < 2; p++) {
                int r = n0 + p * 16 + brow;
                LDSM4(Bh[2 * p][0], Bh[2 * p][1], Bh[2 * p + 1][0], Bh[2 * p + 1][1],
                      bBase + swoff(r, s * 32 + bcb));
                LDSM4(Bl[2 * p][0], Bl[2 * p][1], Bl[2 * p + 1][0], Bl[2 * p + 1][1],
                      bBase + swoff(r, 64 + s * 32 + bcb));
            }
            #pragma unroll
            for (int mt = 0; mt < 4; mt++)
                #pragma unroll
                for (int nt = 0; nt < 4; nt++) {
                    MMA_BF16(d[mt][nt], Ah[mt], Bh[nt]);
                    MMA_BF16(d[mt][nt], Ah[mt], Bl[nt]);
                    MMA_BF16(d[mt][nt], Al[mt], Bh[nt]);
                }
        }

        if (more) {
            int nb = buf ^ 1;
            #pragma unroll
            for (int j = 0; j < 4; j++) {
                int q = tid + j * 256;
                int r = q >> 3, kq = (q & 7) * 4;
                uint32_t h0 = packbf(stA[j].x, stA[j].y);
                uint32_t h1 = packbf(stA[j].z, stA[j].w);
                uint32_t l0 = packbf(stA[j].x - bflo(h0), stA[j].y - bfhi(h0));
                uint32_t l1 = packbf(stA[j].z - bflo(h1), stA[j].w - bfhi(h1));
                *(uint2*)(smem + nb * TILEB + swoff(r, kq * 2))      = make_uint2(h0, h1);
                *(uint2*)(smem + nb * TILEB + swoff(r, 64 + kq * 2)) = make_uint2(l0, l1);
                h0 = packbf(stB[j].x, stB[j].y);
                h1 = packbf(stB[j].z, stB[j].w);
                l0 = packbf(stB[j].x - bflo(h0), stB[j].y - bfhi(h0));
                l1 = packbf(stB[j].z - bflo(h1), stB[j].w - bfhi(h1));
                *(uint2*)(smem + (2 + nb) * TILEB + swoff(r, kq * 2))      = make_uint2(h0, h1);
                *(uint2*)(smem + (2 + nb) * TILEB + swoff(r, 64 + kq * 2)) = make_uint2(l0, l1);
            }
        }
        __syncthreads();
    }

    // ---- C store ----
    #pragma unroll
    for (int mt = 0; mt < 4; mt++) {
        #pragma unroll
        for (int nt = 0; nt < 4; nt++) {
            int row = row0 + m0 + mt * 16 + (lane >> 2);
            int col = col0 + n0 + nt * 8 + (lane & 3) * 2;
            if (row < NR)
                *(float2*)(C + (size_t)row * KO + col) = make_float2(d[mt][nt][0], d[mt][nt][1]);
            if (row + 8 < NR)
                *(float2*)(C + (size_t)(row + 8) * KO + col) = make_float2(d[mt][nt][2], d[mt][nt][3]);
        }
    }

    // ---- fused attention scores over this CTA's 128 cols ----
    float* s_sc = (float*)smem;        // [0,128)=ss  [128,256)=sd
    if (tid < 256) s_sc[tid] = 0.f;
    __syncthreads();

    float ps[4][2] = {}, pd[4][2] = {};
    #pragma unroll
    for (int nt = 0; nt < 4; nt++) {
        int cix = col0 + n0 + nt * 8 + (lane & 3) * 2;
        float a0s = a_s[cix], a1s = a_s[cix + 1];
        float a0d = a_d[cix], a1d = a_d[cix + 1];
        #pragma unroll
        for (int mt = 0; mt < 4; mt++) {
            ps[mt][0] += d[mt][nt][0] * a0s + d[mt][nt][1] * a1s;
            ps[mt][1] += d[mt][nt][2] * a0s + d[mt][nt][3] * a1s;
            pd[mt][0] += d[mt][nt][0] * a0d + d[mt][nt][1] * a1d;
            pd[mt][1] += d[mt][nt][2] * a0d + d[mt][nt][3] * a1d;
        }
    }
    #pragma unroll
    for (int mt = 0; mt < 4; mt++)
        #pragma unroll
        for (int rr = 0; rr < 2; rr++) {
            ps[mt][rr] += __shfl_xor_sync(0xffffffffu, ps[mt][rr], 1);
            ps[mt][rr] += __shfl_xor_sync(0xffffffffu, ps[mt][rr], 2);
            pd[mt][rr] += __shfl_xor_sync(0xffffffffu, pd[mt][rr], 1);
            pd[mt][rr] += __shfl_xor_sync(0xffffffffu, pd[mt][rr], 2);
        }
    if ((lane & 3) == 0) {
        int q = lane >> 2;
        #pragma unroll
        for (int mt = 0; mt < 4; mt++)
            #pragma unroll
            for (int rr = 0; rr < 2; rr++) {
                int r = m0 + mt * 16 + rr * 8 + q;
                atomicAdd(&s_sc[r], ps[mt][rr]);
                atomicAdd(&s_sc[128 + r], pd[mt][rr]);
            }
    }
    __syncthreads();
    if (tid < 128) {
        int gr = row0 + tid;
        if (gr < NR) {
            int head = col0 / headC;
            if (headC == 128) {
                ss[gr * hstr + head] = s_sc[tid];
                sd[gr * hstr + head] = s_sc[128 + tid];
            } else {
                atomicAdd(&ss[gr * hstr + head], s_sc[tid]);
                atomicAdd(&sd[gr * hstr + head], s_sc[128 + tid]);
            }
        }
    }
}

// ---------------- CSR aggregation: softmax + gather-reduce + bias ------------
__global__ void agg_k(const float* __restrict__ hmat,
                      const float* __restrict__ ss, const float* __restrict__ sd,
                      const float* __restrict__ bias, float* __restrict__ out,
                      int heads, int C, int applyLrelu)
{
    __shared__ float s_p[SMAX * NHEADS];
    __shared__ int   s_src[SMAX];
    __shared__ float s_mx[NHEADS], s_den[NHEADS];

    int n = blockIdx.x;
    int tid = threadIdx.x;
    int row0 = g_row[n];
    int deg = g_row[n + 1] - row0;

    int degc = deg < SMAX ? deg : SMAX;
    for (int i = tid; i < degc; i += blockDim.x) s_src[i] = g_srcs[row0 + i];
    __syncthreads();

    int w = tid >> 5, lane = tid & 31;
    if (w < heads) {
        float sdv = sd[n * heads + w];
        float mx = -3.4e38f;
        for (int i = lane; i < deg; i += 32) {
            int s = (i < SMAX) ? s_src[i] : g_srcs[row0 + i];
            float e = lrelu(ss[s * heads + w] + sdv);
            if (i < SMAX) s_p[i * heads + w] = e;
            mx = fmaxf(mx, e);
        }
        #pragma unroll
        for (int o = 16; o; o >>= 1) mx = fmaxf(mx, __shfl_xor_sync(0xffffffffu, mx, o));
        float den = 0.f;
        for (int i = lane; i < deg; i += 32) {
            float e = (i < SMAX) ? s_p[i * heads + w]
                                 : lrelu(ss[g_srcs[row0 + i] * heads + w] + sdv);
            float p = __expf(e - mx);
            if (i < SMAX) s_p[i * heads + w] = p;
            den += p;
        }
        #pragma unroll
        for (int o = 16; o; o >>= 1) den += __shfl_xor_sync(0xffffffffu, den, o);
        if (lane == 0) { s_mx[w] = mx; s_den[w] = den; }
    }
    __syncthreads();

    int cpq = C >> 2;
    int h = tid / cpq;
    int cq = tid - h * cpq;
    float inv = 1.f / (s_den[h] + 1e-16f);
    float4 acc = make_float4(0.f, 0.f, 0.f, 0.f);

    if (deg <= SMAX) {
        const size_t hstr = (size_t)heads * C;
        const int coff = h * C + cq * 4;
        int i = 0;
        for (; i + 8 <= deg; i += 8) {
            int sx[8]; float px[8]; float4 vx[8];
            #pragma unroll
            for (int u = 0; u < 8; u++) { sx[u] = s_src[i + u]; px[u] = s_p[(i + u) * heads + h]; }
            #pragma unroll
            for (int u = 0; u < 8; u++) vx[u] = *(const float4*)(hmat + (size_t)sx[u] * hstr + coff);
            #pragma unroll
            for (int u = 0; u < 8; u++) {
                acc.x += vx[u].x * px[u]; acc.y += vx[u].y * px[u];
                acc.z += vx[u].z * px[u]; acc.w += vx[u].w * px[u];
            }
        }
        for (; i + 4 <= deg; i += 4) {
            int s0 = s_src[i], s1 = s_src[i + 1], s2 = s_src[i + 2], s3 = s_src[i + 3];
            float p0 = s_p[(i + 0) * heads + h], p1 = s_p[(i + 1) * heads + h];
            float p2 = s_p[(i + 2) * heads + h], p3 = s_p[(i + 3) * heads + h];
            float4 v0 = *(const float4*)(hmat + (size_t)s0 * hstr + coff);
            float4 v1 = *(const float4*)(hmat + (size_t)s1 * hstr + coff);
            float4 v2 = *(const float4*)(hmat + (size_t)s2 * hstr + coff);
            float4 v3 = *(const float4*)(hmat + (size_t)s3 * hstr + coff);
            acc.x += v0.x * p0 + v1.x * p1 + v2.x * p2 + v3.x * p3;
            acc.y += v0.y * p0 + v1.y * p1 + v2.y * p2 + v3.y * p3;
            acc.z += v0.z * p0 + v1.z * p1 + v2.z * p2 + v3.z * p3;
            acc.w += v0.w * p0 + v1.w * p1 + v2.w * p2 + v3.w * p3;
        }
        for (; i < deg; i++) {
            int s = s_src[i];
            float p = s_p[i * heads + h];
            float4 v = *(const float4*)(hmat + (size_t)s * hstr + coff);
            acc.x += v.x * p; acc.y += v.y * p; acc.z += v.z * p; acc.w += v.w * p;
        }
    } else {
        float mx = s_mx[h];
        float sdv = sd[n * heads + h];
        for (int i = 0; i < deg; i++) {
            int s = (i < SMAX) ? s_src[i] : g_srcs[row0 + i];
            float p = (i < SMAX) ? s_p[i * heads + h]
                                 : __expf(lrelu(ss[s * heads + h] + sdv) - mx);
            float4 v = *(const float4*)(hmat + ((size_t)s * heads + h) * C + cq * 4);
            acc.x += v.x * p; acc.y += v.y * p; acc.z += v.z * p; acc.w += v.w * p;
        }
    }

    acc.x *= inv; acc.y *= inv; acc.z *= inv; acc.w *= inv;
    int j = h * C + cq * 4;
    float4 bb = *(const float4*)(bias + j);
    acc.x += bb.x; acc.y += bb.y; acc.z += bb.z; acc.w += bb.w;
    if (applyLrelu) {
        acc.x = lrelu(acc.x); acc.y = lrelu(acc.y);
        acc.z = lrelu(acc.z); acc.w = lrelu(acc.w);
    }
    *(float4*)(out + (size_t)n * heads * C + j) = acc;
}

// ---------------- batchnorm --------------------------------------------------
__global__ void bn_stats_k(const float* __restrict__ x, float* __restrict__ bn)
{
    float ls0 = 0.f, ls1 = 0.f, lq0 = 0.f, lq1 = 0.f;
    int t = threadIdx.x;
    for (int n = blockIdx.x; n < NN; n += gridDim.x) {
        const float* r = x + (size_t)n * H1D;
        float v0 = r[t], v1 = r[t + 256];
        ls0 += v0; lq0 += v0 * v0;
        ls1 += v1; lq1 += v1 * v1;
    }
    atomicAdd(bn + t, ls0);             atomicAdd(bn + t + 256, ls1);
    atomicAdd(bn + 512 + t, lq0);       atomicAdd(bn + 512 + t + 256, lq1);
}
__global__ void bn_apply_k(float* __restrict__ x, const float* __restrict__ bn,
                           const float* __restrict__ gamma, const float* __restrict__ beta)
{
    int idx = blockIdx.x * blockDim.x + threadIdx.x;
    if (idx >= NN * H1D) return;
    int c = idx & 511;
    const float invN = 1.0f / NN;
    float mu = bn[c] * invN;
    float var = bn[512 + c] * invN - mu * mu;
    float v = gamma[c] * (x[idx] - mu) * rsqrtf(var + 1e-5f) + beta[c];
    x[idx] = lrelu(v);
}

// ---------------- pooling ----------------------------------------------------
#define PCH 8
__global__ void pool_acc_k(const float* __restrict__ h3, const int* __restrict__ batch,
                           float* __restrict__ out, float* __restrict__ cnt)
{
    int c = threadIdx.x;
    int n0 = blockIdx.x * PCH;
    if (n0 >= NN) return;
    float acc = 0.f, ac = 0.f;
    int curb = batch[n0];
    #pragma unroll
    for (int k = 0; k < PCH; k++) {
        int n = n0 + k;
        if (n >= NN) break;
        int b = batch[n];
        if (b != curb) {
            atomicAdd(out + curb * OUTD + c, acc);
            if (c == 0) atomicAdd(cnt + curb, ac);
            acc = 0.f; ac = 0.f; curb = b;
        }
        acc += h3[(size_t)n * OUTD + c];
        ac += 1.f;
    }
    atomicAdd(out + curb * OUTD + c, acc);
    if (c == 0) atomicAdd(cnt + curb, ac);
}
__global__ void pool_div_k(float* __restrict__ out, const float* __restrict__ cnt)
{
    int i = blockIdx.x * blockDim.x + threadIdx.x;
    if (i >= BB * OUTD) return;
    float c = cnt[i >> 8];
    out[i] /= (c > 1.f ? c : 1.f);
}

// ---------------- host orchestration ----------------------------------------
static inline int ceil_div(int a, int b) { return (a + b - 1) / b; }

extern "C" void kernel_launch(void* const* d_in, const int* in_sizes, int n_in,
                              void* d_out, int out_size)
{
    const float* x      = (const float*)d_in[0];
    const int*   ei     = (const int*)  d_in[1];
    const int*   batch  = (const int*)  d_in[2];
    const float* W1     = (const float*)d_in[3];
    const float* asrc1  = (const float*)d_in[4];
    const float* adst1  = (const float*)d_in[5];
    const float* b1     = (const float*)d_in[6];
    const float* gamma1 = (const float*)d_in[7];
    const float* beta1  = (const float*)d_in[8];
    const float* W2     = (const float*)d_in[9];
    const float* asrc2  = (const float*)d_in[10];
    const float* adst2  = (const float*)d_in[11];
    const float* b2     = (const float*)d_in[12];
    const float* gamma2 = (const float*)d_in[13];
    const float* beta2  = (const float*)d_in[14];
    const float* W3     = (const float*)d_in[15];
    const float* asrc3  = (const float*)d_in[16];
    const float* adst3  = (const float*)d_in[17];
    const float* b3     = (const float*)d_in[18];
    float* out = (float*)d_out;

    float *hB, *featB, *wtB, *ssB, *sdB, *bnB, *cntB;
    int *degB;
    cudaGetSymbolAddress((void**)&hB,    g_h);
    cudaGetSymbolAddress((void**)&featB, g_feat);
    cudaGetSymbolAddress((void**)&wtB,   g_wt);
    cudaGetSymbolAddress((void**)&ssB,   g_ssrc);
    cudaGetSymbolAddress((void**)&sdB,   g_sdst);
    cudaGetSymbolAddress((void**)&bnB,   g_bn);
    cudaGetSymbolAddress((void**)&cntB,  g_cnt);
    cudaGetSymbolAddress((void**)&degB,  g_deg);

    cudaFuncSetAttribute(gemm_mma_k, cudaFuncAttributeMaxDynamicSharedMemorySize, GEMM_SMEM);

    int rowBlocks = ceil_div(NN, 128);

    // ---- CSR build ----
    cudaMemsetAsync(degB, 0, NN * sizeof(int));
    deg_k <<<ceil_div(ET, 256), 256>>>(ei);
    scan_k<<<1, 1024>>>();
    fill_k<<<ceil_div(ET, 256), 256>>>(ei);

    // ================= Layer 1 =================
    transpose_k<<<dim3(H1D / 32, IND / 32), dim3(32, 8)>>>(W1, wtB, IND, H1D);
    gemm_mma_k<<<dim3(H1D / 128, rowBlocks), 256, GEMM_SMEM>>>(
        x, wtB, hB, NN, IND, H1D, asrc1, adst1, ssB, sdB, NHEADS, 128);
    agg_k<<<NN, NHEADS * (HIDC / 4)>>>(hB, ssB, sdB, b1, featB, NHEADS, HIDC, 0);
    cudaMemsetAsync(bnB, 0, 2 * H1D * sizeof(float));
    bn_stats_k<<<256, 256>>>(featB, bnB);
    bn_apply_k<<<ceil_div(NN * H1D, 256), 256>>>(featB, bnB, gamma1, beta1);

    // ================= Layer 2 =================
    transpose_k<<<dim3(H1D / 32, H1D / 32), dim3(32, 8)>>>(W2, wtB, H1D, H1D);
    gemm_mma_k<<<dim3(H1D / 128, rowBlocks), 256, GEMM_SMEM>>>(
        featB, wtB, hB, NN, H1D, H1D, asrc2, adst2, ssB, sdB, NHEADS, 128);
    agg_k<<<NN, NHEADS * (HIDC / 4)>>>(hB, ssB, sdB, b2, featB, NHEADS, HIDC, 0);
    cudaMemsetAsync(bnB, 0, 2 * H1D * sizeof(float));
    bn_stats_k<<<256, 256>>>(featB, bnB);
    bn_apply_k<<<ceil_div(NN * H1D, 256), 256>>>(featB, bnB, gamma2, beta2);

    // ================= Layer 3 =================
    transpose_k<<<dim3(OUTD / 32, H1D / 32), dim3(32, 8)>>>(W3, wtB, H1D, OUTD);
    cudaMemsetAsync(ssB, 0, NN * sizeof(float));
    cudaMemsetAsync(sdB, 0, NN * sizeof(float));
    gemm_mma_k<<<dim3(OUTD / 128, rowBlocks), 256, GEMM_SMEM>>>(
        featB, wtB, hB, NN, H1D, OUTD, asrc3, adst3, ssB, sdB, 1, 256);
    agg_k<<<NN, OUTD / 4>>>(hB, ssB, sdB, b3, featB, 1, OUTD, 1);

    // ================= Global mean pool =================
    cudaMemsetAsync(out, 0, (size_t)BB * OUTD * sizeof(float));
    cudaMemsetAsync(cntB, 0, BB * sizeof(float));
    pool_acc_k<<<ceil_div(NN, PCH), OUTD>>>(featB, batch, out, cntB);
    pool_div_k<<<ceil_div(BB * OUTD, 256), 256>>>(out, cntB);
}